// round 12
// baseline (speedup 1.0000x reference)
#include <cuda_runtime.h>
#include <cuda_fp16.h>
#include <stdint.h>
#include <math.h>

#define B_      32
#define T_      128
#define IN_     512
#define OUT_    512
#define N_      128
#define WD_     64
#define R_      4
#define H_      512
#define IFACE_  471
#define GATES_  2048
#define EPS_    1e-6f
#define LINKS_  132
#define MS_     68
#define CL_     4

__device__ float  g_xz[B_ * T_ * GATES_];     // precomputed x_t @ Wx[0:512,:]
__device__ __half g_wlstm[768 * GATES_];      // rows 0-255: Wx rows 512-767; rows 256-767: Wh
__device__ __half g_wo[768 * OUT_];           // Wo in fp16
__device__ __half g_wif[512 * 480];           // Wif fp16, per-rank 120-col padded slices

struct Smem {
    float M[N_ * MS_];
    float link[N_ * LINKS_];
    float linkT[N_ * LINKS_];
    float act[1280];            // [512:768) reads | [768:1280) h
    float c[128];
    float zbuf[8192];
    float v[472];
    float usage[N_];
    float prec[N_];
    float ww[N_];
    float wr[R_ * N_];
    float Mnorm[N_];
    float skv[N_];
    int   ski[N_];
    float aalloc[N_];
    float cw[N_];
    float crs[R_ * N_];
    float fw[R_ * N_];
    float bw[R_ * N_];
    float erasev[WD_];
    float wvec[WD_];
    float rb[R_];
    float keynorm[R_];
    float modes[R_ * 3];
    float sc[8];
};

__device__ __forceinline__ float sigf(float x) { return 1.f / (1.f + expf(-x)); }
__device__ __forceinline__ float softplusf(float x) {
    return fmaxf(x, 0.f) + log1pf(expf(-fabsf(x)));
}
__device__ __forceinline__ float warp_sum(float v) {
    #pragma unroll
    for (int o = 16; o; o >>= 1) v += __shfl_xor_sync(0xffffffffu, v, o);
    return v;
}
__device__ __forceinline__ float warp_max(float v) {
    #pragma unroll
    for (int o = 16; o; o >>= 1) v = fmaxf(v, __shfl_xor_sync(0xffffffffu, v, o));
    return v;
}
__device__ __forceinline__ void cluster_sync() {
    asm volatile("barrier.cluster.arrive.aligned;" ::: "memory");
    asm volatile("barrier.cluster.wait.aligned;" ::: "memory");
}
__device__ __forceinline__ float dsmem_ld(const float* p, int rank) {
    uint32_t la = (uint32_t)__cvta_generic_to_shared((void*)p);
    uint32_t ra;
    asm("mapa.shared::cluster.u32 %0, %1, %2;" : "=r"(ra) : "r"(la), "r"(rank));
    float val;
    asm volatile("ld.shared::cluster.f32 %0, [%1];" : "=f"(val) : "r"(ra));
    return val;
}
__device__ __forceinline__ float dot4(float4 a, float4 b) {
    return fmaf(a.x, b.x, fmaf(a.y, b.y, fmaf(a.z, b.z, a.w * b.w)));
}

// ---------------- weight conversion kernels ----------------
__global__ void __launch_bounds__(1024) cvt_lstm(const float* __restrict__ Wx,
                                                 const float* __restrict__ Wh) {
    int idx2 = (blockIdx.x * 1024 + threadIdx.x) * 2;
    if (idx2 >= 768 * GATES_) return;
    int row = idx2 >> 11, col = idx2 & 2047;
    const float* src = (row < 256) ? (Wx + (size_t)(512 + row) * GATES_ + col)
                                   : (Wh + (size_t)(row - 256) * GATES_ + col);
    *reinterpret_cast<__half2*>(&g_wlstm[idx2]) = __floats2half2_rn(src[0], src[1]);
}
__global__ void __launch_bounds__(1024) cvt_wo(const float* __restrict__ Wo) {
    int idx2 = (blockIdx.x * 1024 + threadIdx.x) * 2;
    if (idx2 >= 768 * OUT_) return;
    *reinterpret_cast<__half2*>(&g_wo[idx2]) = __floats2half2_rn(Wo[idx2], Wo[idx2 + 1]);
}
__global__ void __launch_bounds__(1024) cvt_wif(const float* __restrict__ Wif) {
    int idx = blockIdx.x * 1024 + threadIdx.x;
    if (idx >= 512 * 480) return;
    int row = idx / 480, c = idx % 480;
    int rank = c / 120, cc = c % 120;
    int ncols = (rank < 3) ? 118 : 117;
    float val = (cc < ncols) ? Wif[(size_t)row * IFACE_ + rank * 118 + cc] : 0.f;
    g_wif[idx] = __float2half_rn(val);
}

// ---------------- precompute kernel: g_xz = x @ Wx[0:512,:] ----------------
// 128x128 block tile, K-tile 16, 8x8 per thread (split 4+4 for conflict-free LDS.128)
__global__ void __launch_bounds__(256) xz_kernel(const float* __restrict__ x,
                                                 const float* __restrict__ Wx) {
    __shared__ float xsT[16][132];   // transposed x tile: xsT[k][row]
    __shared__ float ws[16][132];    // w tile: ws[k][col]
    const int rb = blockIdx.x * 128;
    const int cb = blockIdx.y * 128;
    const int tid = threadIdx.x;
    const int tr0 = (tid >> 4) * 4;  // 0..60
    const int tc0 = (tid & 15) * 4;  // 0..60

    float acc[8][8];
    #pragma unroll
    for (int i = 0; i < 8; i++)
        #pragma unroll
        for (int j = 0; j < 8; j++) acc[i][j] = 0.f;

    for (int kt = 0; kt < IN_; kt += 16) {
        // x tile: 128 rows x 16 k -> transposed. 512 float4 loads, 2/thread.
        #pragma unroll
        for (int l = 0; l < 2; l++) {
            int idx = tid + l * 256;
            int row = idx >> 2;
            int k4  = (idx & 3) * 4;
            float4 xv = *reinterpret_cast<const float4*>(&x[(size_t)(rb + row) * IN_ + kt + k4]);
            xsT[k4 + 0][row] = xv.x; xsT[k4 + 1][row] = xv.y;
            xsT[k4 + 2][row] = xv.z; xsT[k4 + 3][row] = xv.w;
        }
        // w tile: 16 k x 128 cols. 512 float4 loads, 2/thread.
        #pragma unroll
        for (int l = 0; l < 2; l++) {
            int idx = tid + l * 256;
            int kk = idx >> 5;
            int c4 = (idx & 31) * 4;
            *reinterpret_cast<float4*>(&ws[kk][c4]) =
                *reinterpret_cast<const float4*>(&Wx[(size_t)(kt + kk) * GATES_ + cb + c4]);
        }
        __syncthreads();
        #pragma unroll
        for (int kk = 0; kk < 16; kk++) {
            float xr[8], wc[8];
            *reinterpret_cast<float4*>(&xr[0]) = *reinterpret_cast<float4*>(&xsT[kk][tr0]);
            *reinterpret_cast<float4*>(&xr[4]) = *reinterpret_cast<float4*>(&xsT[kk][tr0 + 64]);
            *reinterpret_cast<float4*>(&wc[0]) = *reinterpret_cast<float4*>(&ws[kk][tc0]);
            *reinterpret_cast<float4*>(&wc[4]) = *reinterpret_cast<float4*>(&ws[kk][tc0 + 64]);
            #pragma unroll
            for (int i = 0; i < 8; i++)
                #pragma unroll
                for (int j = 0; j < 8; j++)
                    acc[i][j] = fmaf(xr[i], wc[j], acc[i][j]);
        }
        __syncthreads();
    }
    #pragma unroll
    for (int i = 0; i < 8; i++) {
        int row = rb + ((i < 4) ? (tr0 + i) : (64 + tr0 + i - 4));
        float4* d0 = reinterpret_cast<float4*>(&g_xz[(size_t)row * GATES_ + cb + tc0]);
        float4* d1 = reinterpret_cast<float4*>(&g_xz[(size_t)row * GATES_ + cb + 64 + tc0]);
        *d0 = make_float4(acc[i][0], acc[i][1], acc[i][2], acc[i][3]);
        *d1 = make_float4(acc[i][4], acc[i][5], acc[i][6], acc[i][7]);
    }
}

// ---------------- main recurrent kernel ----------------
__global__ void __launch_bounds__(1024, 1) __cluster_dims__(CL_, 1, 1) dnc_kernel(
    const float* __restrict__ bl,
    const float* __restrict__ bif,
    const float* __restrict__ bo,
    float* __restrict__ out)
{
    extern __shared__ char smraw[];
    Smem& s = *reinterpret_cast<Smem*>(smraw);
    const int tid  = threadIdx.x;
    const int lane = tid & 31;
    const int wi   = tid >> 5;
    uint32_t krank_u;
    asm("mov.u32 %0, %%cluster_ctarank;" : "=r"(krank_u));
    const int k = (int)krank_u;
    const int b = blockIdx.x >> 2;

    for (int i = tid; i < N_ * MS_;    i += 1024) s.M[i]     = 0.f;
    for (int i = tid; i < N_ * LINKS_; i += 1024) { s.link[i] = 0.f; s.linkT[i] = 0.f; }
    for (int i = tid; i < 1280;        i += 1024) s.act[i]   = 0.f;
    if (tid < 128) s.c[tid] = 0.f;
    if (tid < N_) { s.usage[tid] = 0.f; s.prec[tid] = 0.f; s.ww[tid] = 0.f; s.Mnorm[tid] = 0.f; }
    for (int i = tid; i < R_ * N_; i += 1024) s.wr[i] = 0.f;
    __syncthreads();

    for (int t = 0; t < T_; t++) {
        float xz0 = 0.f, xz1 = 0.f, xz2 = 0.f, xz3 = 0.f;
        if (tid < 128) {
            const float* xzr = g_xz + (size_t)(b * T_ + t) * GATES_;
            int jg = k * 128 + tid;
            xz0 = xzr[jg]; xz1 = xzr[512 + jg]; xz2 = xzr[1024 + jg]; xz3 = xzr[1536 + jg];
        }

        // ==== P1: LSTM GEMM (tid<768) || out GEMM of t-1 (tid>=768) ====
        if (tid < 768) {
            const int g    = tid & 63;
            const int part = tid >> 6;
            const int gate = g >> 4;
            const int cg8  = (g & 15) * 8;
            const int colg = gate * 512 + k * 128 + cg8;
            float a0 = 0.f, a1 = 0.f, a2 = 0.f, a3 = 0.f;
            float a4 = 0.f, a5 = 0.f, a6 = 0.f, a7 = 0.f;
            const int r0 = part * 64;
            #pragma unroll 8
            for (int i = r0; i < r0 + 64; i++) {
                float sv = s.act[512 + i];
                uint4 wp = *reinterpret_cast<const uint4*>(&g_wlstm[(size_t)i * GATES_ + colg]);
                const __half2* h2 = reinterpret_cast<const __half2*>(&wp);
                float2 f0 = __half22float2(h2[0]);
                float2 f1 = __half22float2(h2[1]);
                float2 f2 = __half22float2(h2[2]);
                float2 f3 = __half22float2(h2[3]);
                a0 = fmaf(sv, f0.x, a0); a1 = fmaf(sv, f0.y, a1);
                a2 = fmaf(sv, f1.x, a2); a3 = fmaf(sv, f1.y, a3);
                a4 = fmaf(sv, f2.x, a4); a5 = fmaf(sv, f2.y, a5);
                a6 = fmaf(sv, f3.x, a6); a7 = fmaf(sv, f3.y, a7);
            }
            const int cl = gate * 128 + cg8;
            *reinterpret_cast<float4*>(&s.zbuf[part * 512 + cl])     = make_float4(a0, a1, a2, a3);
            *reinterpret_cast<float4*>(&s.zbuf[part * 512 + cl + 4]) = make_float4(a4, a5, a6, a7);
        } else if (t > 0) {
            const int q    = tid - 768;
            const int grp  = q & 15;
            const int part = q >> 4;
            const int cg8  = grp * 8;
            const int colg = k * 128 + cg8;
            float a0 = 0.f, a1 = 0.f, a2 = 0.f, a3 = 0.f;
            float a4 = 0.f, a5 = 0.f, a6 = 0.f, a7 = 0.f;
            const int r0 = part * 48;
            #pragma unroll 8
            for (int i = r0; i < r0 + 48; i++) {
                float sv = s.act[512 + i];
                uint4 wp = *reinterpret_cast<const uint4*>(&g_wo[(size_t)i * OUT_ + colg]);
                const __half2* h2 = reinterpret_cast<const __half2*>(&wp);
                float2 f0 = __half22float2(h2[0]);
                float2 f1 = __half22float2(h2[1]);
                float2 f2 = __half22float2(h2[2]);
                float2 f3 = __half22float2(h2[3]);
                a0 = fmaf(sv, f0.x, a0); a1 = fmaf(sv, f0.y, a1);
                a2 = fmaf(sv, f1.x, a2); a3 = fmaf(sv, f1.y, a3);
                a4 = fmaf(sv, f2.x, a4); a5 = fmaf(sv, f2.y, a5);
                a6 = fmaf(sv, f3.x, a6); a7 = fmaf(sv, f3.y, a7);
            }
            *reinterpret_cast<float4*>(&s.zbuf[6144 + part * 128 + cg8])     = make_float4(a0, a1, a2, a3);
            *reinterpret_cast<float4*>(&s.zbuf[6144 + part * 128 + cg8 + 4]) = make_float4(a4, a5, a6, a7);
        }
        __syncthreads();

        // ==== P2: gate reduce || out reduce+store ====
        if (tid < 512) {
            float acc = s.zbuf[tid];
            #pragma unroll
            for (int p = 1; p < 12; p++) acc += s.zbuf[p * 512 + tid];
            s.zbuf[tid] = acc;
        } else if (t > 0 && tid < 640) {
            const int o = tid - 512;
            float acc = bo[k * 128 + o];
            #pragma unroll
            for (int p = 0; p < 16; p++) acc += s.zbuf[6144 + p * 128 + o];
            out[(size_t)b * T_ * OUT_ + (size_t)(t - 1) * OUT_ + k * 128 + o] = acc;
        }
        __syncthreads();

        // ==== P3: LSTM pointwise ====
        if (tid < 128) {
            const int j  = tid;
            const int jg = k * 128 + j;
            float zi = s.zbuf[j]        + xz0 + bl[jg];
            float zf = s.zbuf[128 + j]  + xz1 + bl[512 + jg];
            float zg = s.zbuf[256 + j]  + xz2 + bl[1024 + jg];
            float zo = s.zbuf[384 + j]  + xz3 + bl[1536 + jg];
            float cn = sigf(zf) * s.c[j] + sigf(zi) * tanhf(zg);
            s.c[j] = cn;
            s.act[768 + jg] = sigf(zo) * tanhf(cn);
        }
        cluster_sync();   // S1
        if (tid < 128) {
            #pragma unroll
            for (int p = 0; p < CL_; p++)
                if (p != k) s.act[768 + p * 128 + tid] = dsmem_ld(&s.act[768 + p * 128 + tid], p);
        }
        __syncthreads();

        // ==== P4: iface GEMM slice (fp16) ====
        if (tid < 960) {
            const int grp  = tid % 15;
            const int part = tid / 15;
            const int cg8  = grp * 8;
            float a0 = 0.f, a1 = 0.f, a2 = 0.f, a3 = 0.f;
            float a4 = 0.f, a5 = 0.f, a6 = 0.f, a7 = 0.f;
            const int r0 = part * 8;
            #pragma unroll
            for (int i = r0; i < r0 + 8; i++) {
                float sv = s.act[768 + i];
                uint4 wp = *reinterpret_cast<const uint4*>(&g_wif[(size_t)i * 480 + k * 120 + cg8]);
                const __half2* h2 = reinterpret_cast<const __half2*>(&wp);
                float2 f0 = __half22float2(h2[0]);
                float2 f1 = __half22float2(h2[1]);
                float2 f2 = __half22float2(h2[2]);
                float2 f3 = __half22float2(h2[3]);
                a0 = fmaf(sv, f0.x, a0); a1 = fmaf(sv, f0.y, a1);
                a2 = fmaf(sv, f1.x, a2); a3 = fmaf(sv, f1.y, a3);
                a4 = fmaf(sv, f2.x, a4); a5 = fmaf(sv, f2.y, a5);
                a6 = fmaf(sv, f3.x, a6); a7 = fmaf(sv, f3.y, a7);
            }
            *reinterpret_cast<float4*>(&s.zbuf[part * 120 + cg8])     = make_float4(a0, a1, a2, a3);
            *reinterpret_cast<float4*>(&s.zbuf[part * 120 + cg8 + 4]) = make_float4(a4, a5, a6, a7);
        }
        __syncthreads();
        {
            const int base  = k * 118;
            const int ncols = (k < 3) ? 118 : 117;
            if (tid < ncols) {
                float acc = 0.f;
                #pragma unroll 8
                for (int p = 0; p < 64; p++) acc += s.zbuf[p * 120 + tid];
                s.v[base + tid] = acc + bif[base + tid];
            }
        }
        cluster_sync();   // S2
        if (tid < IFACE_) {
            const int owner = tid / 118;
            if (owner != k) s.v[tid] = dsmem_ld(&s.v[tid], owner);
        }
        __syncthreads();

        // ==== X1 ====
        if (tid < 128) {
            float f0 = sigf(s.v[453]), f1 = sigf(s.v[454]), f2 = sigf(s.v[455]), f3 = sigf(s.v[456]);
            float ret = (1.f - f0 * s.wr[tid]) * (1.f - f1 * s.wr[128 + tid])
                      * (1.f - f2 * s.wr[256 + tid]) * (1.f - f3 * s.wr[384 + tid]);
            float u = s.usage[tid], w0 = s.ww[tid];
            s.usage[tid] = (u + w0 - u * w0) * ret;
        } else if (tid < 256) {
            int n = tid - 128;
            const float4* mr = reinterpret_cast<const float4*>(&s.M[n * MS_]);
            const float4* kr = reinterpret_cast<const float4*>(&s.v[260]);
            float d = 0.f;
            #pragma unroll
            for (int q = 0; q < 16; q++) d += dot4(mr[q], kr[q]);
            s.cw[n] = d / (s.Mnorm[n] + EPS_);
        } else if (wi >= 8 && wi < 12) {
            int r = wi - 8;
            float kv = s.v[r * 64 + lane], kv2 = s.v[r * 64 + lane + 32];
            float ssum = warp_sum(kv * kv + kv2 * kv2);
            if (lane == 0) s.keynorm[r] = sqrtf(ssum);
        } else if (wi == 12) {
            float kv = s.v[260 + lane], kv2 = s.v[260 + lane + 32];
            float ssum = warp_sum(kv * kv + kv2 * kv2);
            if (lane == 0) s.sc[3] = sqrtf(ssum);
        } else if (tid >= 416 && tid < 480) {
            int w = tid - 416;
            s.erasev[w] = sigf(s.v[325 + w]);
            s.wvec[w]   = s.v[389 + w];
        } else if (tid >= 480 && tid < 484) {
            int r = tid - 480;
            float m0 = s.v[459 + 3 * r], m1 = s.v[460 + 3 * r], m2 = s.v[461 + 3 * r];
            float mx = fmaxf(m0, fmaxf(m1, m2));
            float e0 = expf(m0 - mx), e1 = expf(m1 - mx), e2 = expf(m2 - mx);
            float ssum = e0 + e1 + e2;
            s.modes[3 * r] = e0 / ssum; s.modes[3 * r + 1] = e1 / ssum; s.modes[3 * r + 2] = e2 / ssum;
        } else if (tid >= 484 && tid < 488) {
            int r = tid - 484;
            s.rb[r] = 1.f + softplusf(s.v[256 + r]);
        } else if (tid == 488) s.sc[0] = 1.f + softplusf(s.v[324]);
        else if (tid == 489) s.sc[1] = sigf(s.v[457]);
        else if (tid == 490) s.sc[2] = sigf(s.v[458]);
        __syncthreads();

        // ==== X2 ====
        if (wi == 0) {
            float tsc = s.sc[0] / (s.sc[3] + EPS_);
            float a0 = s.cw[lane] * tsc,      a1 = s.cw[lane + 32] * tsc;
            float a2 = s.cw[lane + 64] * tsc, a3 = s.cw[lane + 96] * tsc;
            float mx = warp_max(fmaxf(fmaxf(a0, a1), fmaxf(a2, a3)));
            float e0 = expf(a0 - mx), e1 = expf(a1 - mx), e2 = expf(a2 - mx), e3 = expf(a3 - mx);
            float su = warp_sum(e0 + e1 + e2 + e3);
            float inv = 1.f / su;
            s.cw[lane] = e0 * inv; s.cw[lane + 32] = e1 * inv;
            s.cw[lane + 64] = e2 * inv; s.cw[lane + 96] = e3 * inv;
        } else if (tid >= 128 && tid < 256) {
            int e = tid - 128;
            float ue = s.usage[e];
            int cnt = 0;
            #pragma unroll 8
            for (int j = 0; j < 128; j++) {
                float uj = s.usage[j];
                cnt += (uj < ue) || (uj == ue && j < e);
            }
            s.skv[cnt] = ue; s.ski[cnt] = e;
        }
        __syncthreads();

        // ==== X3+X4 ====
        if (wi == 0) {
            float running = 1.f;
            #pragma unroll
            for (int r = 0; r < 4; r++) {
                float v0 = s.skv[r * 32 + lane];
                int   ix = s.ski[r * 32 + lane];
                float c = v0;
                #pragma unroll
                for (int off = 1; off < 32; off <<= 1) {
                    float tsh = __shfl_up_sync(0xffffffffu, c, off);
                    if (lane >= off) c *= tsh;
                }
                float excl_in = __shfl_up_sync(0xffffffffu, c, 1);
                float excl = (lane == 0) ? running : excl_in * running;
                s.aalloc[ix] = (1.f - v0) * excl;
                running *= __shfl_sync(0xffffffffu, c, 31);
            }
            __syncwarp();
            float ag = s.sc[1], wg = s.sc[2];
            #pragma unroll
            for (int o = 0; o < 4; o++) {
                int n = lane + o * 32;
                s.ww[n] = wg * (ag * s.aalloc[n] + (1.f - ag) * s.cw[n]);
            }
        }
        __syncthreads();

        // ==== X5+X6 ====
        {
            const int ti = (tid >> 5) * 4;
            const int tj = (tid & 31) * 4;
            float wwi[4], nv[4][4];
            #pragma unroll
            for (int r = 0; r < 4; r++) wwi[r] = s.ww[ti + r];
            float4 wwj4 = *reinterpret_cast<const float4*>(&s.ww[tj]);
            float4 pj4  = *reinterpret_cast<const float4*>(&s.prec[tj]);
            #pragma unroll
            for (int r = 0; r < 4; r++) {
                float4 lo = *reinterpret_cast<const float4*>(&s.link[(ti + r) * LINKS_ + tj]);
                nv[r][0] = (1.f - wwi[r] - wwj4.x) * lo.x + wwi[r] * pj4.x;
                nv[r][1] = (1.f - wwi[r] - wwj4.y) * lo.y + wwi[r] * pj4.y;
                nv[r][2] = (1.f - wwi[r] - wwj4.z) * lo.z + wwi[r] * pj4.z;
                nv[r][3] = (1.f - wwi[r] - wwj4.w) * lo.w + wwi[r] * pj4.w;
                #pragma unroll
                for (int cc = 0; cc < 4; cc++)
                    if (ti + r == tj + cc) nv[r][cc] = 0.f;
                *reinterpret_cast<float4*>(&s.link[(ti + r) * LINKS_ + tj]) =
                    make_float4(nv[r][0], nv[r][1], nv[r][2], nv[r][3]);
            }
            #pragma unroll
            for (int cc = 0; cc < 4; cc++)
                *reinterpret_cast<float4*>(&s.linkT[(tj + cc) * LINKS_ + ti]) =
                    make_float4(nv[0][cc], nv[1][cc], nv[2][cc], nv[3][cc]);
        }
        if (tid < 512) {
            const int row = tid >> 2, sub = tid & 3;
            const int w0 = sub * 16;
            float wwn = s.ww[row];
            float sq = 0.f;
            #pragma unroll
            for (int q = 0; q < 4; q++) {
                float4 m  = *reinterpret_cast<const float4*>(&s.M[row * MS_ + w0 + q * 4]);
                float4 ev = *reinterpret_cast<const float4*>(&s.erasev[w0 + q * 4]);
                float4 wv = *reinterpret_cast<const float4*>(&s.wvec[w0 + q * 4]);
                m.x = m.x * (1.f - wwn * ev.x) + wwn * wv.x;
                m.y = m.y * (1.f - wwn * ev.y) + wwn * wv.y;
                m.z = m.z * (1.f - wwn * ev.z) + wwn * wv.z;
                m.w = m.w * (1.f - wwn * ev.w) + wwn * wv.w;
                sq += m.x * m.x + m.y * m.y + m.z * m.z + m.w * m.w;
                *reinterpret_cast<float4*>(&s.M[row * MS_ + w0 + q * 4]) = m;
            }
            sq += __shfl_xor_sync(0xffffffffu, sq, 1);
            sq += __shfl_xor_sync(0xffffffffu, sq, 2);
            if (sub == 0) s.Mnorm[row] = sqrtf(sq);
        } else if (wi == 16) {
            float ssum = warp_sum(s.ww[lane] + s.ww[lane + 32] + s.ww[lane + 64] + s.ww[lane + 96]);
            if (lane == 0) s.sc[4] = ssum;
        }
        __syncthreads();

        // ==== X7+X8 ====
        if (tid < 512) {
            const int r = tid >> 7, i = tid & 127;
            const float4* lr  = reinterpret_cast<const float4*>(&s.link[i * LINKS_]);
            const float4* wrr = reinterpret_cast<const float4*>(&s.wr[r * 128]);
            float acc = 0.f;
            #pragma unroll
            for (int q = 0; q < 32; q++) acc += dot4(lr[q], wrr[q]);
            s.fw[tid] = acc;
            const int n = i;
            const float4* mr = reinterpret_cast<const float4*>(&s.M[n * MS_]);
            const float4* kr = reinterpret_cast<const float4*>(&s.v[r * 64]);
            float d = 0.f;
            #pragma unroll
            for (int q = 0; q < 16; q++) d += dot4(mr[q], kr[q]);
            s.crs[tid] = s.rb[r] * d / ((s.Mnorm[n] + EPS_) * (s.keynorm[r] + EPS_));
        } else {
            const int q2 = tid - 512;
            const int r = q2 >> 7, i = q2 & 127;
            const float4* lr  = reinterpret_cast<const float4*>(&s.linkT[i * LINKS_]);
            const float4* wrr = reinterpret_cast<const float4*>(&s.wr[r * 128]);
            float acc = 0.f;
            #pragma unroll
            for (int q = 0; q < 32; q++) acc += dot4(lr[q], wrr[q]);
            s.bw[q2] = acc;
        }
        __syncthreads();

        // ==== X9+X10 ====
        if (wi < 4) {
            int r = wi;
            float a0 = s.crs[r * N_ + lane],      a1 = s.crs[r * N_ + lane + 32];
            float a2 = s.crs[r * N_ + lane + 64], a3 = s.crs[r * N_ + lane + 96];
            float mx = warp_max(fmaxf(fmaxf(a0, a1), fmaxf(a2, a3)));
            float e0 = expf(a0 - mx), e1 = expf(a1 - mx), e2 = expf(a2 - mx), e3 = expf(a3 - mx);
            float su = warp_sum(e0 + e1 + e2 + e3);
            float inv = 1.f / su;
            float m0 = s.modes[3 * r], m1 = s.modes[3 * r + 1], m2 = s.modes[3 * r + 2];
            #pragma unroll
            for (int o = 0; o < 4; o++) {
                int n = lane + o * 32;
                float cv = (o == 0 ? e0 : o == 1 ? e1 : o == 2 ? e2 : e3) * inv;
                s.wr[r * 128 + n] = m0 * s.bw[r * 128 + n] + m1 * cv + m2 * s.fw[r * 128 + n];
            }
        } else if (wi == 4) {
            float ssum = s.sc[4];
            #pragma unroll
            for (int o = 0; o < 4; o++) {
                int n = lane + o * 32;
                s.prec[n] = (1.f - ssum) * s.prec[n] + s.ww[n];
            }
        }
        __syncthreads();

        // ==== X11 ====
        {
            int outi = tid & 255;
            int chunk = tid >> 8;
            int r = outi >> 6, w = outi & 63;
            float acc = 0.f;
            int n0 = chunk * 32;
            #pragma unroll 4
            for (int n = n0; n < n0 + 32; n++)
                acc = fmaf(s.wr[r * 128 + n], s.M[n * MS_ + w], acc);
            s.zbuf[chunk * 256 + outi] = acc;
        }
        __syncthreads();
        if (tid < 256)
            s.act[512 + tid] = s.zbuf[tid] + s.zbuf[256 + tid] + s.zbuf[512 + tid] + s.zbuf[768 + tid];
        __syncthreads();
    }

    // ==== final out GEMM for t = T-1 ====
    {
        const int grp  = tid & 15;
        const int part = tid >> 4;
        const int cg8  = grp * 8;
        const int colg = k * 128 + cg8;
        float a0 = 0.f, a1 = 0.f, a2 = 0.f, a3 = 0.f;
        float a4 = 0.f, a5 = 0.f, a6 = 0.f, a7 = 0.f;
        const int r0 = part * 12;
        #pragma unroll
        for (int i = r0; i < r0 + 12; i++) {
            float sv = s.act[512 + i];
            uint4 wp = *reinterpret_cast<const uint4*>(&g_wo[(size_t)i * OUT_ + colg]);
            const __half2* h2 = reinterpret_cast<const __half2*>(&wp);
            float2 f0 = __half22float2(h2[0]);
            float2 f1 = __half22float2(h2[1]);
            float2 f2 = __half22float2(h2[2]);
            float2 f3 = __half22float2(h2[3]);
            a0 = fmaf(sv, f0.x, a0); a1 = fmaf(sv, f0.y, a1);
            a2 = fmaf(sv, f1.x, a2); a3 = fmaf(sv, f1.y, a3);
            a4 = fmaf(sv, f2.x, a4); a5 = fmaf(sv, f2.y, a5);
            a6 = fmaf(sv, f3.x, a6); a7 = fmaf(sv, f3.y, a7);
        }
        *reinterpret_cast<float4*>(&s.zbuf[part * 128 + cg8])     = make_float4(a0, a1, a2, a3);
        *reinterpret_cast<float4*>(&s.zbuf[part * 128 + cg8 + 4]) = make_float4(a4, a5, a6, a7);
    }
    __syncthreads();
    if (tid < 128) {
        float acc = bo[k * 128 + tid];
        #pragma unroll
        for (int p = 0; p < 64; p++) acc += s.zbuf[p * 128 + tid];
        out[(size_t)b * T_ * OUT_ + (size_t)(T_ - 1) * OUT_ + k * 128 + tid] = acc;
    }
}

extern "C" void kernel_launch(void* const* d_in, const int* in_sizes, int n_in,
                              void* d_out, int out_size) {
    (void)in_sizes; (void)n_in; (void)out_size;
    const float* x   = (const float*)d_in[0];
    const float* Wx  = (const float*)d_in[1];
    const float* Wh  = (const float*)d_in[2];
    const float* bl  = (const float*)d_in[3];
    const float* Wif = (const float*)d_in[4];
    const float* bif = (const float*)d_in[5];
    const float* Wo  = (const float*)d_in[6];
    const float* bo  = (const float*)d_in[7];
    float* out = (float*)d_out;

    cvt_lstm<<<(768 * GATES_ / 2 + 1023) / 1024, 1024>>>(Wx, Wh);
    cvt_wo<<<(768 * OUT_ / 2 + 1023) / 1024, 1024>>>(Wo);
    cvt_wif<<<(512 * 480 + 1023) / 1024, 1024>>>(Wif);

    dim3 pg(B_ * T_ / 128, GATES_ / 128);
    xz_kernel<<<pg, 256>>>(x, Wx);

    cudaFuncSetAttribute(dnc_kernel, cudaFuncAttributeMaxDynamicSharedMemorySize,
                         (int)sizeof(Smem));
    dnc_kernel<<<B_ * CL_, 1024, sizeof(Smem)>>>(bl, bif, bo, out);
}

// round 13
// speedup vs baseline: 1.5591x; 1.5591x over previous
#include <cuda_runtime.h>
#include <cuda_fp16.h>
#include <stdint.h>
#include <math.h>

#define B_      32
#define T_      128
#define IN_     512
#define OUT_    512
#define N_      128
#define WD_     64
#define R_      4
#define H_      512
#define IFACE_  471
#define GATES_  2048
#define EPS_    1e-6f
#define LINKS_  132
#define MS_     68
#define CL_     4

__device__ float  g_xz[B_ * T_ * GATES_];     // precomputed x_t @ Wx[0:512,:]
__device__ __half g_wlstm[768 * GATES_];      // rows 0-255: Wx rows 512-767; rows 256-767: Wh
__device__ __half g_wo[768 * OUT_];           // Wo in fp16
__device__ __half g_wif[512 * 480];           // Wif fp16, per-rank 120-col padded slices

struct Smem {
    float M[N_ * MS_];
    float link[N_ * LINKS_];
    float linkT[N_ * LINKS_];
    float act[1280];            // [512:768) reads | [768:1280) h
    float c[128];
    float zbuf[8192];
    float v[472];
    float usage[N_];
    float prec[N_];
    float ww[N_];
    float wr[R_ * N_];
    float Mnorm[N_];
    float skv[N_];
    int   ski[N_];
    float aalloc[N_];
    float cw[N_];
    float crs[R_ * N_];
    float crsb[R_ * N_];
    float fw[R_ * N_];
    float bw[R_ * N_];
    float erasev[WD_];
    float wvec[WD_];
    float rb[R_];
    float keynorm[R_];
    float modes[R_ * 3];
    float sc[8];
};

__device__ __forceinline__ float sigf(float x) { return 1.f / (1.f + expf(-x)); }
__device__ __forceinline__ float softplusf(float x) {
    return fmaxf(x, 0.f) + log1pf(expf(-fabsf(x)));
}
__device__ __forceinline__ float warp_sum(float v) {
    #pragma unroll
    for (int o = 16; o; o >>= 1) v += __shfl_xor_sync(0xffffffffu, v, o);
    return v;
}
__device__ __forceinline__ float warp_max(float v) {
    #pragma unroll
    for (int o = 16; o; o >>= 1) v = fmaxf(v, __shfl_xor_sync(0xffffffffu, v, o));
    return v;
}
__device__ __forceinline__ void cluster_sync() {
    asm volatile("barrier.cluster.arrive.aligned;" ::: "memory");
    asm volatile("barrier.cluster.wait.aligned;" ::: "memory");
}
__device__ __forceinline__ float dsmem_ld(const float* p, int rank) {
    uint32_t la = (uint32_t)__cvta_generic_to_shared((void*)p);
    uint32_t ra;
    asm("mapa.shared::cluster.u32 %0, %1, %2;" : "=r"(ra) : "r"(la), "r"(rank));
    float val;
    asm volatile("ld.shared::cluster.f32 %0, [%1];" : "=f"(val) : "r"(ra));
    return val;
}
__device__ __forceinline__ float dot4(float4 a, float4 b) {
    return fmaf(a.x, b.x, fmaf(a.y, b.y, fmaf(a.z, b.z, a.w * b.w)));
}

// ---------------- weight conversion kernels ----------------
__global__ void __launch_bounds__(1024) cvt_lstm(const float* __restrict__ Wx,
                                                 const float* __restrict__ Wh) {
    int idx2 = (blockIdx.x * 1024 + threadIdx.x) * 2;
    if (idx2 >= 768 * GATES_) return;
    int row = idx2 >> 11, col = idx2 & 2047;
    const float* src = (row < 256) ? (Wx + (size_t)(512 + row) * GATES_ + col)
                                   : (Wh + (size_t)(row - 256) * GATES_ + col);
    *reinterpret_cast<__half2*>(&g_wlstm[idx2]) = __floats2half2_rn(src[0], src[1]);
}
__global__ void __launch_bounds__(1024) cvt_wo(const float* __restrict__ Wo) {
    int idx2 = (blockIdx.x * 1024 + threadIdx.x) * 2;
    if (idx2 >= 768 * OUT_) return;
    *reinterpret_cast<__half2*>(&g_wo[idx2]) = __floats2half2_rn(Wo[idx2], Wo[idx2 + 1]);
}
__global__ void __launch_bounds__(1024) cvt_wif(const float* __restrict__ Wif) {
    int idx = blockIdx.x * 1024 + threadIdx.x;
    if (idx >= 512 * 480) return;
    int row = idx / 480, c = idx % 480;
    int rank = c / 120, cc = c % 120;
    int ncols = (rank < 3) ? 118 : 117;
    float val = (cc < ncols) ? Wif[(size_t)row * IFACE_ + rank * 118 + cc] : 0.f;
    g_wif[idx] = __float2half_rn(val);
}

// ---------------- precompute kernel: g_xz = x @ Wx[0:512,:]  (R11 version) ----------------
__global__ void __launch_bounds__(256) xz_kernel(const float* __restrict__ x,
                                                 const float* __restrict__ Wx) {
    __shared__ float xs[32][33];
    __shared__ float ws[32][264];
    const int rb = blockIdx.x;
    const int cb = blockIdx.y;
    const int tid = threadIdx.x;
    const int ty = tid >> 5;
    const int tx = tid & 31;

    float acc[4][8];
    #pragma unroll
    for (int i = 0; i < 4; i++)
        #pragma unroll
        for (int j = 0; j < 8; j++) acc[i][j] = 0.f;

    for (int kt = 0; kt < IN_; kt += 32) {
        for (int i = tid; i < 1024; i += 256) {
            int r = i >> 5, cc = i & 31;
            xs[r][cc] = x[(size_t)(rb * 32 + r) * IN_ + kt + cc];
        }
        for (int i = tid; i < 2048; i += 256) {
            int kk = i >> 6, c4 = (i & 63) * 4;
            *reinterpret_cast<float4*>(&ws[kk][c4]) =
                *reinterpret_cast<const float4*>(Wx + (size_t)(kt + kk) * GATES_ + cb * 256 + c4);
        }
        __syncthreads();
        #pragma unroll 8
        for (int kk = 0; kk < 32; kk++) {
            float4 w0 = *reinterpret_cast<float4*>(&ws[kk][tx * 8]);
            float4 w1 = *reinterpret_cast<float4*>(&ws[kk][tx * 8 + 4]);
            #pragma unroll
            for (int i = 0; i < 4; i++) {
                float xv = xs[ty * 4 + i][kk];
                acc[i][0] = fmaf(xv, w0.x, acc[i][0]); acc[i][1] = fmaf(xv, w0.y, acc[i][1]);
                acc[i][2] = fmaf(xv, w0.z, acc[i][2]); acc[i][3] = fmaf(xv, w0.w, acc[i][3]);
                acc[i][4] = fmaf(xv, w1.x, acc[i][4]); acc[i][5] = fmaf(xv, w1.y, acc[i][5]);
                acc[i][6] = fmaf(xv, w1.z, acc[i][6]); acc[i][7] = fmaf(xv, w1.w, acc[i][7]);
            }
        }
        __syncthreads();
    }
    #pragma unroll
    for (int i = 0; i < 4; i++) {
        size_t row = (size_t)(rb * 32 + ty * 4 + i);
        float4* dst = reinterpret_cast<float4*>(&g_xz[row * GATES_ + cb * 256 + tx * 8]);
        dst[0] = make_float4(acc[i][0], acc[i][1], acc[i][2], acc[i][3]);
        dst[1] = make_float4(acc[i][4], acc[i][5], acc[i][6], acc[i][7]);
    }
}

// ---------------- main recurrent kernel ----------------
__global__ void __launch_bounds__(1024, 1) __cluster_dims__(CL_, 1, 1) dnc_kernel(
    const float* __restrict__ bl,
    const float* __restrict__ bif,
    const float* __restrict__ bo,
    float* __restrict__ out)
{
    extern __shared__ char smraw[];
    Smem& s = *reinterpret_cast<Smem*>(smraw);
    const int tid  = threadIdx.x;
    const int lane = tid & 31;
    const int wi   = tid >> 5;
    uint32_t krank_u;
    asm("mov.u32 %0, %%cluster_ctarank;" : "=r"(krank_u));
    const int k = (int)krank_u;
    const int b = blockIdx.x >> 2;

    for (int i = tid; i < N_ * MS_;    i += 1024) s.M[i]     = 0.f;
    for (int i = tid; i < N_ * LINKS_; i += 1024) { s.link[i] = 0.f; s.linkT[i] = 0.f; }
    for (int i = tid; i < 1280;        i += 1024) s.act[i]   = 0.f;
    if (tid < 128) s.c[tid] = 0.f;
    if (tid < N_) { s.usage[tid] = 0.f; s.prec[tid] = 0.f; s.ww[tid] = 0.f; s.Mnorm[tid] = 0.f; }
    for (int i = tid; i < R_ * N_; i += 1024) s.wr[i] = 0.f;
    __syncthreads();

    for (int t = 0; t < T_; t++) {
        float xz0 = 0.f, xz1 = 0.f, xz2 = 0.f, xz3 = 0.f;
        if (tid < 128) {
            const float* xzr = g_xz + (size_t)(b * T_ + t) * GATES_;
            int jg = k * 128 + tid;
            xz0 = xzr[jg]; xz1 = xzr[512 + jg]; xz2 = xzr[1024 + jg]; xz3 = xzr[1536 + jg];
        }

        // ==== P1: LSTM GEMM (tid<768) || out GEMM of t-1 (tid>=768) ====
        if (tid < 768) {
            const int g    = tid & 63;
            const int part = tid >> 6;
            const int gate = g >> 4;
            const int cg8  = (g & 15) * 8;
            const int colg = gate * 512 + k * 128 + cg8;
            float a0 = 0.f, a1 = 0.f, a2 = 0.f, a3 = 0.f;
            float a4 = 0.f, a5 = 0.f, a6 = 0.f, a7 = 0.f;
            const int r0 = part * 64;
            #pragma unroll 8
            for (int i = r0; i < r0 + 64; i++) {
                float sv = s.act[512 + i];
                uint4 wp = *reinterpret_cast<const uint4*>(&g_wlstm[(size_t)i * GATES_ + colg]);
                const __half2* h2 = reinterpret_cast<const __half2*>(&wp);
                float2 f0 = __half22float2(h2[0]);
                float2 f1 = __half22float2(h2[1]);
                float2 f2 = __half22float2(h2[2]);
                float2 f3 = __half22float2(h2[3]);
                a0 = fmaf(sv, f0.x, a0); a1 = fmaf(sv, f0.y, a1);
                a2 = fmaf(sv, f1.x, a2); a3 = fmaf(sv, f1.y, a3);
                a4 = fmaf(sv, f2.x, a4); a5 = fmaf(sv, f2.y, a5);
                a6 = fmaf(sv, f3.x, a6); a7 = fmaf(sv, f3.y, a7);
            }
            const int cl = gate * 128 + cg8;
            *reinterpret_cast<float4*>(&s.zbuf[part * 512 + cl])     = make_float4(a0, a1, a2, a3);
            *reinterpret_cast<float4*>(&s.zbuf[part * 512 + cl + 4]) = make_float4(a4, a5, a6, a7);
        } else if (t > 0) {
            const int q    = tid - 768;
            const int grp  = q & 15;
            const int part = q >> 4;
            const int cg8  = grp * 8;
            const int colg = k * 128 + cg8;
            float a0 = 0.f, a1 = 0.f, a2 = 0.f, a3 = 0.f;
            float a4 = 0.f, a5 = 0.f, a6 = 0.f, a7 = 0.f;
            const int r0 = part * 48;
            #pragma unroll 8
            for (int i = r0; i < r0 + 48; i++) {
                float sv = s.act[512 + i];
                uint4 wp = *reinterpret_cast<const uint4*>(&g_wo[(size_t)i * OUT_ + colg]);
                const __half2* h2 = reinterpret_cast<const __half2*>(&wp);
                float2 f0 = __half22float2(h2[0]);
                float2 f1 = __half22float2(h2[1]);
                float2 f2 = __half22float2(h2[2]);
                float2 f3 = __half22float2(h2[3]);
                a0 = fmaf(sv, f0.x, a0); a1 = fmaf(sv, f0.y, a1);
                a2 = fmaf(sv, f1.x, a2); a3 = fmaf(sv, f1.y, a3);
                a4 = fmaf(sv, f2.x, a4); a5 = fmaf(sv, f2.y, a5);
                a6 = fmaf(sv, f3.x, a6); a7 = fmaf(sv, f3.y, a7);
            }
            *reinterpret_cast<float4*>(&s.zbuf[6144 + part * 128 + cg8])     = make_float4(a0, a1, a2, a3);
            *reinterpret_cast<float4*>(&s.zbuf[6144 + part * 128 + cg8 + 4]) = make_float4(a4, a5, a6, a7);
        }
        __syncthreads();

        // ==== P2: gate reduce || out reduce+store ====
        if (tid < 512) {
            float acc = s.zbuf[tid];
            #pragma unroll
            for (int p = 1; p < 12; p++) acc += s.zbuf[p * 512 + tid];
            s.zbuf[tid] = acc;
        } else if (t > 0 && tid < 640) {
            const int o = tid - 512;
            float acc = bo[k * 128 + o];
            #pragma unroll
            for (int p = 0; p < 16; p++) acc += s.zbuf[6144 + p * 128 + o];
            out[(size_t)b * T_ * OUT_ + (size_t)(t - 1) * OUT_ + k * 128 + o] = acc;
        }
        __syncthreads();

        // ==== P3: LSTM pointwise ====
        if (tid < 128) {
            const int j  = tid;
            const int jg = k * 128 + j;
            float zi = s.zbuf[j]        + xz0 + bl[jg];
            float zf = s.zbuf[128 + j]  + xz1 + bl[512 + jg];
            float zg = s.zbuf[256 + j]  + xz2 + bl[1024 + jg];
            float zo = s.zbuf[384 + j]  + xz3 + bl[1536 + jg];
            float cn = sigf(zf) * s.c[j] + sigf(zi) * tanhf(zg);
            s.c[j] = cn;
            s.act[768 + jg] = sigf(zo) * tanhf(cn);
        }
        cluster_sync();   // S1
        if (tid < 128) {
            #pragma unroll
            for (int p = 0; p < CL_; p++)
                if (p != k) s.act[768 + p * 128 + tid] = dsmem_ld(&s.act[768 + p * 128 + tid], p);
        }
        __syncthreads();

        // ==== P4: iface GEMM slice (fp16) ====
        if (tid < 960) {
            const int grp  = tid % 15;
            const int part = tid / 15;
            const int cg8  = grp * 8;
            float a0 = 0.f, a1 = 0.f, a2 = 0.f, a3 = 0.f;
            float a4 = 0.f, a5 = 0.f, a6 = 0.f, a7 = 0.f;
            const int r0 = part * 8;
            #pragma unroll
            for (int i = r0; i < r0 + 8; i++) {
                float sv = s.act[768 + i];
                uint4 wp = *reinterpret_cast<const uint4*>(&g_wif[(size_t)i * 480 + k * 120 + cg8]);
                const __half2* h2 = reinterpret_cast<const __half2*>(&wp);
                float2 f0 = __half22float2(h2[0]);
                float2 f1 = __half22float2(h2[1]);
                float2 f2 = __half22float2(h2[2]);
                float2 f3 = __half22float2(h2[3]);
                a0 = fmaf(sv, f0.x, a0); a1 = fmaf(sv, f0.y, a1);
                a2 = fmaf(sv, f1.x, a2); a3 = fmaf(sv, f1.y, a3);
                a4 = fmaf(sv, f2.x, a4); a5 = fmaf(sv, f2.y, a5);
                a6 = fmaf(sv, f3.x, a6); a7 = fmaf(sv, f3.y, a7);
            }
            *reinterpret_cast<float4*>(&s.zbuf[part * 120 + cg8])     = make_float4(a0, a1, a2, a3);
            *reinterpret_cast<float4*>(&s.zbuf[part * 120 + cg8 + 4]) = make_float4(a4, a5, a6, a7);
        }
        __syncthreads();
        {
            const int base  = k * 118;
            const int ncols = (k < 3) ? 118 : 117;
            if (tid < ncols) {
                float acc = 0.f;
                #pragma unroll 8
                for (int p = 0; p < 64; p++) acc += s.zbuf[p * 120 + tid];
                s.v[base + tid] = acc + bif[base + tid];
            }
        }
        cluster_sync();   // S2
        if (tid < IFACE_) {
            const int owner = tid / 118;
            if (owner != k) s.v[tid] = dsmem_ld(&s.v[tid], owner);
        }
        __syncthreads();

        // ==== X1 ====
        if (tid < 128) {
            float f0 = sigf(s.v[453]), f1 = sigf(s.v[454]), f2 = sigf(s.v[455]), f3 = sigf(s.v[456]);
            float ret = (1.f - f0 * s.wr[tid]) * (1.f - f1 * s.wr[128 + tid])
                      * (1.f - f2 * s.wr[256 + tid]) * (1.f - f3 * s.wr[384 + tid]);
            float u = s.usage[tid], w0 = s.ww[tid];
            s.usage[tid] = (u + w0 - u * w0) * ret;
        } else if (tid < 256) {
            int n = tid - 128;
            const float4* mr = reinterpret_cast<const float4*>(&s.M[n * MS_]);
            const float4* kr = reinterpret_cast<const float4*>(&s.v[260]);
            float d = 0.f;
            #pragma unroll
            for (int q = 0; q < 16; q++) d += dot4(mr[q], kr[q]);
            s.cw[n] = d / (s.Mnorm[n] + EPS_);
        } else if (wi >= 8 && wi < 12) {
            int r = wi - 8;
            float kv = s.v[r * 64 + lane], kv2 = s.v[r * 64 + lane + 32];
            float ssum = warp_sum(kv * kv + kv2 * kv2);
            if (lane == 0) s.keynorm[r] = sqrtf(ssum);
        } else if (wi == 12) {
            float kv = s.v[260 + lane], kv2 = s.v[260 + lane + 32];
            float ssum = warp_sum(kv * kv + kv2 * kv2);
            if (lane == 0) s.sc[3] = sqrtf(ssum);
        } else if (tid >= 416 && tid < 480) {
            int w = tid - 416;
            s.erasev[w] = sigf(s.v[325 + w]);
            s.wvec[w]   = s.v[389 + w];
        } else if (tid >= 480 && tid < 484) {
            int r = tid - 480;
            float m0 = s.v[459 + 3 * r], m1 = s.v[460 + 3 * r], m2 = s.v[461 + 3 * r];
            float mx = fmaxf(m0, fmaxf(m1, m2));
            float e0 = expf(m0 - mx), e1 = expf(m1 - mx), e2 = expf(m2 - mx);
            float ssum = e0 + e1 + e2;
            s.modes[3 * r] = e0 / ssum; s.modes[3 * r + 1] = e1 / ssum; s.modes[3 * r + 2] = e2 / ssum;
        } else if (tid >= 484 && tid < 488) {
            int r = tid - 484;
            s.rb[r] = 1.f + softplusf(s.v[256 + r]);
        } else if (tid == 488) s.sc[0] = 1.f + softplusf(s.v[324]);
        else if (tid == 489) s.sc[1] = sigf(s.v[457]);
        else if (tid == 490) s.sc[2] = sigf(s.v[458]);
        __syncthreads();

        // ==== X2 ====
        if (wi == 0) {
            float tsc = s.sc[0] / (s.sc[3] + EPS_);
            float a0 = s.cw[lane] * tsc,      a1 = s.cw[lane + 32] * tsc;
            float a2 = s.cw[lane + 64] * tsc, a3 = s.cw[lane + 96] * tsc;
            float mx = warp_max(fmaxf(fmaxf(a0, a1), fmaxf(a2, a3)));
            float e0 = expf(a0 - mx), e1 = expf(a1 - mx), e2 = expf(a2 - mx), e3 = expf(a3 - mx);
            float su = warp_sum(e0 + e1 + e2 + e3);
            float inv = 1.f / su;
            s.cw[lane] = e0 * inv; s.cw[lane + 32] = e1 * inv;
            s.cw[lane + 64] = e2 * inv; s.cw[lane + 96] = e3 * inv;
        } else if (tid >= 128 && tid < 256) {
            int e = tid - 128;
            float ue = s.usage[e];
            int cnt = 0;
            #pragma unroll 8
            for (int j = 0; j < 128; j++) {
                float uj = s.usage[j];
                cnt += (uj < ue) || (uj == ue && j < e);
            }
            s.skv[cnt] = ue; s.ski[cnt] = e;
        }
        __syncthreads();

        // ==== X3+X4 ====
        if (wi == 0) {
            float running = 1.f;
            #pragma unroll
            for (int r = 0; r < 4; r++) {
                float v0 = s.skv[r * 32 + lane];
                int   ix = s.ski[r * 32 + lane];
                float c = v0;
                #pragma unroll
                for (int off = 1; off < 32; off <<= 1) {
                    float tsh = __shfl_up_sync(0xffffffffu, c, off);
                    if (lane >= off) c *= tsh;
                }
                float excl_in = __shfl_up_sync(0xffffffffu, c, 1);
                float excl = (lane == 0) ? running : excl_in * running;
                s.aalloc[ix] = (1.f - v0) * excl;
                running *= __shfl_sync(0xffffffffu, c, 31);
            }
            __syncwarp();
            float ag = s.sc[1], wg = s.sc[2];
            #pragma unroll
            for (int o = 0; o < 4; o++) {
                int n = lane + o * 32;
                s.ww[n] = wg * (ag * s.aalloc[n] + (1.f - ag) * s.cw[n]);
            }
        }
        __syncthreads();

        // ==== X5+X6 ====
        {
            const int ti = (tid >> 5) * 4;
            const int tj = (tid & 31) * 4;
            float wwi[4], nv[4][4];
            #pragma unroll
            for (int r = 0; r < 4; r++) wwi[r] = s.ww[ti + r];
            float4 wwj4 = *reinterpret_cast<const float4*>(&s.ww[tj]);
            float4 pj4  = *reinterpret_cast<const float4*>(&s.prec[tj]);
            #pragma unroll
            for (int r = 0; r < 4; r++) {
                float4 lo = *reinterpret_cast<const float4*>(&s.link[(ti + r) * LINKS_ + tj]);
                nv[r][0] = (1.f - wwi[r] - wwj4.x) * lo.x + wwi[r] * pj4.x;
                nv[r][1] = (1.f - wwi[r] - wwj4.y) * lo.y + wwi[r] * pj4.y;
                nv[r][2] = (1.f - wwi[r] - wwj4.z) * lo.z + wwi[r] * pj4.z;
                nv[r][3] = (1.f - wwi[r] - wwj4.w) * lo.w + wwi[r] * pj4.w;
                #pragma unroll
                for (int cc = 0; cc < 4; cc++)
                    if (ti + r == tj + cc) nv[r][cc] = 0.f;
                *reinterpret_cast<float4*>(&s.link[(ti + r) * LINKS_ + tj]) =
                    make_float4(nv[r][0], nv[r][1], nv[r][2], nv[r][3]);
            }
            #pragma unroll
            for (int cc = 0; cc < 4; cc++)
                *reinterpret_cast<float4*>(&s.linkT[(tj + cc) * LINKS_ + ti]) =
                    make_float4(nv[0][cc], nv[1][cc], nv[2][cc], nv[3][cc]);
        }
        if (tid < 512) {
            const int row = tid >> 2, sub = tid & 3;
            const int w0 = sub * 16;
            float wwn = s.ww[row];
            float sq = 0.f;
            #pragma unroll
            for (int q = 0; q < 4; q++) {
                float4 m  = *reinterpret_cast<const float4*>(&s.M[row * MS_ + w0 + q * 4]);
                float4 ev = *reinterpret_cast<const float4*>(&s.erasev[w0 + q * 4]);
                float4 wv = *reinterpret_cast<const float4*>(&s.wvec[w0 + q * 4]);
                m.x = m.x * (1.f - wwn * ev.x) + wwn * wv.x;
                m.y = m.y * (1.f - wwn * ev.y) + wwn * wv.y;
                m.z = m.z * (1.f - wwn * ev.z) + wwn * wv.z;
                m.w = m.w * (1.f - wwn * ev.w) + wwn * wv.w;
                sq += m.x * m.x + m.y * m.y + m.z * m.z + m.w * m.w;
                *reinterpret_cast<float4*>(&s.M[row * MS_ + w0 + q * 4]) = m;
            }
            sq += __shfl_xor_sync(0xffffffffu, sq, 1);
            sq += __shfl_xor_sync(0xffffffffu, sq, 2);
            if (sub == 0) s.Mnorm[row] = sqrtf(sq);
        } else if (wi == 16) {
            float ssum = warp_sum(s.ww[lane] + s.ww[lane + 32] + s.ww[lane + 64] + s.ww[lane + 96]);
            if (lane == 0) s.sc[4] = ssum;
        }
        __syncthreads();

        // ==== X7+X8: fw + crs(q=0..7) on tid<512; bw + crs(q=8..15) on tid>=512 ====
        if (tid < 512) {
            const int r = tid >> 7, i = tid & 127;
            const float4* lr  = reinterpret_cast<const float4*>(&s.link[i * LINKS_]);
            const float4* wrr = reinterpret_cast<const float4*>(&s.wr[r * 128]);
            float acc = 0.f;
            #pragma unroll
            for (int q = 0; q < 32; q++) acc += dot4(lr[q], wrr[q]);
            s.fw[tid] = acc;
            const float4* mr = reinterpret_cast<const float4*>(&s.M[i * MS_]);
            const float4* kr = reinterpret_cast<const float4*>(&s.v[r * 64]);
            float d = 0.f;
            #pragma unroll
            for (int q = 0; q < 8; q++) d += dot4(mr[q], kr[q]);
            float scale = s.rb[r] / ((s.Mnorm[i] + EPS_) * (s.keynorm[r] + EPS_));
            s.crs[tid] = scale * d;
        } else {
            const int q2 = tid - 512;
            const int r = q2 >> 7, i = q2 & 127;
            const float4* lr  = reinterpret_cast<const float4*>(&s.linkT[i * LINKS_]);
            const float4* wrr = reinterpret_cast<const float4*>(&s.wr[r * 128]);
            float acc = 0.f;
            #pragma unroll
            for (int q = 0; q < 32; q++) acc += dot4(lr[q], wrr[q]);
            s.bw[q2] = acc;
            const float4* mr = reinterpret_cast<const float4*>(&s.M[i * MS_]);
            const float4* kr = reinterpret_cast<const float4*>(&s.v[r * 64]);
            float d = 0.f;
            #pragma unroll
            for (int q = 8; q < 16; q++) d += dot4(mr[q], kr[q]);
            float scale = s.rb[r] / ((s.Mnorm[i] + EPS_) * (s.keynorm[r] + EPS_));
            s.crsb[q2] = scale * d;
        }
        __syncthreads();

        // ==== X9+X10: per-r read softmax + wr write (warps 0-3) || prec update (warp 4) ====
        if (wi < 4) {
            int r = wi;
            float a0 = s.crs[r * N_ + lane]      + s.crsb[r * N_ + lane];
            float a1 = s.crs[r * N_ + lane + 32] + s.crsb[r * N_ + lane + 32];
            float a2 = s.crs[r * N_ + lane + 64] + s.crsb[r * N_ + lane + 64];
            float a3 = s.crs[r * N_ + lane + 96] + s.crsb[r * N_ + lane + 96];
            float mx = warp_max(fmaxf(fmaxf(a0, a1), fmaxf(a2, a3)));
            float e0 = expf(a0 - mx), e1 = expf(a1 - mx), e2 = expf(a2 - mx), e3 = expf(a3 - mx);
            float su = warp_sum(e0 + e1 + e2 + e3);
            float inv = 1.f / su;
            float m0 = s.modes[3 * r], m1 = s.modes[3 * r + 1], m2 = s.modes[3 * r + 2];
            #pragma unroll
            for (int o = 0; o < 4; o++) {
                int n = lane + o * 32;
                float cv = (o == 0 ? e0 : o == 1 ? e1 : o == 2 ? e2 : e3) * inv;
                s.wr[r * 128 + n] = m0 * s.bw[r * 128 + n] + m1 * cv + m2 * s.fw[r * 128 + n];
            }
        } else if (wi == 4) {
            float ssum = s.sc[4];
            #pragma unroll
            for (int o = 0; o < 4; o++) {
                int n = lane + o * 32;
                s.prec[n] = (1.f - ssum) * s.prec[n] + s.ww[n];
            }
        }
        __syncthreads();

        // ==== X11: reads_n = wr_n @ M ====
        {
            int outi = tid & 255;
            int chunk = tid >> 8;
            int r = outi >> 6, w = outi & 63;
            float acc = 0.f;
            int n0 = chunk * 32;
            #pragma unroll 4
            for (int n = n0; n < n0 + 32; n++)
                acc = fmaf(s.wr[r * 128 + n], s.M[n * MS_ + w], acc);
            s.zbuf[chunk * 256 + outi] = acc;
        }
        __syncthreads();
        if (tid < 256)
            s.act[512 + tid] = s.zbuf[tid] + s.zbuf[256 + tid] + s.zbuf[512 + tid] + s.zbuf[768 + tid];
        __syncthreads();
    }

    // ==== final out GEMM for t = T-1 ====
    {
        const int grp  = tid & 15;
        const int part = tid >> 4;
        const int cg8  = grp * 8;
        const int colg = k * 128 + cg8;
        float a0 = 0.f, a1 = 0.f, a2 = 0.f, a3 = 0.f;
        float a4 = 0.f, a5 = 0.f, a6 = 0.f, a7 = 0.f;
        const int r0 = part * 12;
        #pragma unroll
        for (int i = r0; i < r0 + 12; i++) {
            float sv = s.act[512 + i];
            uint4 wp = *reinterpret_cast<const uint4*>(&g_wo[(size_t)i * OUT_ + colg]);
            const __half2* h2 = reinterpret_cast<const __half2*>(&wp);
            float2 f0 = __half22float2(h2[0]);
            float2 f1 = __half22float2(h2[1]);
            float2 f2 = __half22float2(h2[2]);
            float2 f3 = __half22float2(h2[3]);
            a0 = fmaf(sv, f0.x, a0); a1 = fmaf(sv, f0.y, a1);
            a2 = fmaf(sv, f1.x, a2); a3 = fmaf(sv, f1.y, a3);
            a4 = fmaf(sv, f2.x, a4); a5 = fmaf(sv, f2.y, a5);
            a6 = fmaf(sv, f3.x, a6); a7 = fmaf(sv, f3.y, a7);
        }
        *reinterpret_cast<float4*>(&s.zbuf[part * 128 + cg8])     = make_float4(a0, a1, a2, a3);
        *reinterpret_cast<float4*>(&s.zbuf[part * 128 + cg8 + 4]) = make_float4(a4, a5, a6, a7);
    }
    __syncthreads();
    if (tid < 128) {
        float acc = bo[k * 128 + tid];
        #pragma unroll
        for (int p = 0; p < 64; p++) acc += s.zbuf[p * 128 + tid];
        out[(size_t)b * T_ * OUT_ + (size_t)(T_ - 1) * OUT_ + k * 128 + tid] = acc;
    }
}

extern "C" void kernel_launch(void* const* d_in, const int* in_sizes, int n_in,
                              void* d_out, int out_size) {
    (void)in_sizes; (void)n_in; (void)out_size;
    const float* x   = (const float*)d_in[0];
    const float* Wx  = (const float*)d_in[1];
    const float* Wh  = (const float*)d_in[2];
    const float* bl  = (const float*)d_in[3];
    const float* Wif = (const float*)d_in[4];
    const float* bif = (const float*)d_in[5];
    const float* Wo  = (const float*)d_in[6];
    const float* bo  = (const float*)d_in[7];
    float* out = (float*)d_out;

    cvt_lstm<<<(768 * GATES_ / 2 + 1023) / 1024, 1024>>>(Wx, Wh);
    cvt_wo<<<(768 * OUT_ / 2 + 1023) / 1024, 1024>>>(Wo);
    cvt_wif<<<(512 * 480 + 1023) / 1024, 1024>>>(Wif);

    dim3 pg(B_ * T_ / 32, GATES_ / 256);
    xz_kernel<<<pg, 256>>>(x, Wx);

    cudaFuncSetAttribute(dnc_kernel, cudaFuncAttributeMaxDynamicSharedMemorySize,
                         (int)sizeof(Smem));
    dnc_kernel<<<B_ * CL_, 1024, sizeof(Smem)>>>(bl, bif, bo, out);
}

// round 14
// speedup vs baseline: 1.6391x; 1.0513x over previous
#include <cuda_runtime.h>
#include <cuda_fp16.h>
#include <stdint.h>
#include <math.h>

#define B_      32
#define T_      128
#define IN_     512
#define OUT_    512
#define N_      128
#define WD_     64
#define R_      4
#define H_      512
#define IFACE_  471
#define GATES_  2048
#define EPS_    1e-6f
#define LINKS_  132
#define MS_     68
#define CL_     4

__device__ float  g_xz[B_ * T_ * GATES_];     // precomputed x_t @ Wx[0:512,:]
__device__ __half g_wlstm[768 * GATES_];      // rows 0-255: Wx rows 512-767; rows 256-767: Wh
__device__ __half g_wo[768 * OUT_];           // Wo in fp16
__device__ __half g_wif[512 * 480];           // Wif fp16, per-rank 120-col padded slices

struct Smem {
    float M[N_ * MS_];
    float link[N_ * LINKS_];
    float linkT[N_ * LINKS_];
    float act[1280];            // [512:768) reads | [768:1280) h
    float c[128];
    float zbuf[8192];
    float v[472];
    float usage[N_];
    float prec[N_];
    float ww[N_];
    float wr[R_ * N_];
    float Mnorm[N_];
    float skv[N_];
    int   ski[N_];
    float aalloc[N_];
    float cw[N_];
    float crs[R_ * N_];
    float crsb[R_ * N_];
    float fw[R_ * N_];
    float bw[R_ * N_];
    float erasev[WD_];
    float wvec[WD_];
    float rb[R_];
    float keynorm[R_];
    float modes[R_ * 3];
    float sc[8];
};

__device__ __forceinline__ float sigf(float x) { return 1.f / (1.f + expf(-x)); }
__device__ __forceinline__ float softplusf(float x) {
    return fmaxf(x, 0.f) + log1pf(expf(-fabsf(x)));
}
__device__ __forceinline__ float warp_sum(float v) {
    #pragma unroll
    for (int o = 16; o; o >>= 1) v += __shfl_xor_sync(0xffffffffu, v, o);
    return v;
}
__device__ __forceinline__ float warp_max(float v) {
    #pragma unroll
    for (int o = 16; o; o >>= 1) v = fmaxf(v, __shfl_xor_sync(0xffffffffu, v, o));
    return v;
}
__device__ __forceinline__ void cluster_sync() {
    asm volatile("barrier.cluster.arrive.aligned;" ::: "memory");
    asm volatile("barrier.cluster.wait.aligned;" ::: "memory");
}
__device__ __forceinline__ float dsmem_ld(const float* p, int rank) {
    uint32_t la = (uint32_t)__cvta_generic_to_shared((void*)p);
    uint32_t ra;
    asm("mapa.shared::cluster.u32 %0, %1, %2;" : "=r"(ra) : "r"(la), "r"(rank));
    float val;
    asm volatile("ld.shared::cluster.f32 %0, [%1];" : "=f"(val) : "r"(ra));
    return val;
}
__device__ __forceinline__ float dot4(float4 a, float4 b) {
    return fmaf(a.x, b.x, fmaf(a.y, b.y, fmaf(a.z, b.z, a.w * b.w)));
}

// ---------------- weight conversion kernels ----------------
__global__ void __launch_bounds__(1024) cvt_lstm(const float* __restrict__ Wx,
                                                 const float* __restrict__ Wh) {
    int idx2 = (blockIdx.x * 1024 + threadIdx.x) * 2;
    if (idx2 >= 768 * GATES_) return;
    int row = idx2 >> 11, col = idx2 & 2047;
    const float* src = (row < 256) ? (Wx + (size_t)(512 + row) * GATES_ + col)
                                   : (Wh + (size_t)(row - 256) * GATES_ + col);
    *reinterpret_cast<__half2*>(&g_wlstm[idx2]) = __floats2half2_rn(src[0], src[1]);
}
__global__ void __launch_bounds__(1024) cvt_wo(const float* __restrict__ Wo) {
    int idx2 = (blockIdx.x * 1024 + threadIdx.x) * 2;
    if (idx2 >= 768 * OUT_) return;
    *reinterpret_cast<__half2*>(&g_wo[idx2]) = __floats2half2_rn(Wo[idx2], Wo[idx2 + 1]);
}
__global__ void __launch_bounds__(1024) cvt_wif(const float* __restrict__ Wif) {
    int idx = blockIdx.x * 1024 + threadIdx.x;
    if (idx >= 512 * 480) return;
    int row = idx / 480, c = idx % 480;
    int rank = c / 120, cc = c % 120;
    int ncols = (rank < 3) ? 118 : 117;
    float val = (cc < ncols) ? Wif[(size_t)row * IFACE_ + rank * 118 + cc] : 0.f;
    g_wif[idx] = __float2half_rn(val);
}

// ---------------- precompute kernel: g_xz = x @ Wx[0:512,:] ----------------
// 128x128 block tile, K-tile 16, 8x8 per thread (split 4+4 for conflict-free LDS.128)
__global__ void __launch_bounds__(256) xz_kernel(const float* __restrict__ x,
                                                 const float* __restrict__ Wx) {
    __shared__ float xsT[16][132];   // transposed x tile: xsT[k][row]
    __shared__ float ws[16][132];    // w tile: ws[k][col]
    const int rb = blockIdx.x * 128;
    const int cb = blockIdx.y * 128;
    const int tid = threadIdx.x;
    const int tr0 = (tid >> 4) * 4;  // 0..60
    const int tc0 = (tid & 15) * 4;  // 0..60

    float acc[8][8];
    #pragma unroll
    for (int i = 0; i < 8; i++)
        #pragma unroll
        for (int j = 0; j < 8; j++) acc[i][j] = 0.f;

    for (int kt = 0; kt < IN_; kt += 16) {
        #pragma unroll
        for (int l = 0; l < 2; l++) {
            int idx = tid + l * 256;
            int row = idx >> 2;
            int k4  = (idx & 3) * 4;
            float4 xv = *reinterpret_cast<const float4*>(&x[(size_t)(rb + row) * IN_ + kt + k4]);
            xsT[k4 + 0][row] = xv.x; xsT[k4 + 1][row] = xv.y;
            xsT[k4 + 2][row] = xv.z; xsT[k4 + 3][row] = xv.w;
        }
        #pragma unroll
        for (int l = 0; l < 2; l++) {
            int idx = tid + l * 256;
            int kk = idx >> 5;
            int c4 = (idx & 31) * 4;
            *reinterpret_cast<float4*>(&ws[kk][c4]) =
                *reinterpret_cast<const float4*>(&Wx[(size_t)(kt + kk) * GATES_ + cb + c4]);
        }
        __syncthreads();
        #pragma unroll
        for (int kk = 0; kk < 16; kk++) {
            float xr[8], wc[8];
            *reinterpret_cast<float4*>(&xr[0]) = *reinterpret_cast<float4*>(&xsT[kk][tr0]);
            *reinterpret_cast<float4*>(&xr[4]) = *reinterpret_cast<float4*>(&xsT[kk][tr0 + 64]);
            *reinterpret_cast<float4*>(&wc[0]) = *reinterpret_cast<float4*>(&ws[kk][tc0]);
            *reinterpret_cast<float4*>(&wc[4]) = *reinterpret_cast<float4*>(&ws[kk][tc0 + 64]);
            #pragma unroll
            for (int i = 0; i < 8; i++)
                #pragma unroll
                for (int j = 0; j < 8; j++)
                    acc[i][j] = fmaf(xr[i], wc[j], acc[i][j]);
        }
        __syncthreads();
    }
    #pragma unroll
    for (int i = 0; i < 8; i++) {
        int row = rb + ((i < 4) ? (tr0 + i) : (64 + tr0 + i - 4));
        float4* d0 = reinterpret_cast<float4*>(&g_xz[(size_t)row * GATES_ + cb + tc0]);
        float4* d1 = reinterpret_cast<float4*>(&g_xz[(size_t)row * GATES_ + cb + 64 + tc0]);
        *d0 = make_float4(acc[i][0], acc[i][1], acc[i][2], acc[i][3]);
        *d1 = make_float4(acc[i][4], acc[i][5], acc[i][6], acc[i][7]);
    }
}

// ---------------- main recurrent kernel ----------------
__global__ void __launch_bounds__(1024, 1) __cluster_dims__(CL_, 1, 1) dnc_kernel(
    const float* __restrict__ bl,
    const float* __restrict__ bif,
    const float* __restrict__ bo,
    float* __restrict__ out)
{
    extern __shared__ char smraw[];
    Smem& s = *reinterpret_cast<Smem*>(smraw);
    const int tid  = threadIdx.x;
    const int lane = tid & 31;
    const int wi   = tid >> 5;
    uint32_t krank_u;
    asm("mov.u32 %0, %%cluster_ctarank;" : "=r"(krank_u));
    const int k = (int)krank_u;
    const int b = blockIdx.x >> 2;

    for (int i = tid; i < N_ * MS_;    i += 1024) s.M[i]     = 0.f;
    for (int i = tid; i < N_ * LINKS_; i += 1024) { s.link[i] = 0.f; s.linkT[i] = 0.f; }
    for (int i = tid; i < 1280;        i += 1024) s.act[i]   = 0.f;
    if (tid < 128) s.c[tid] = 0.f;
    if (tid < N_) { s.usage[tid] = 0.f; s.prec[tid] = 0.f; s.ww[tid] = 0.f; s.Mnorm[tid] = 0.f; }
    for (int i = tid; i < R_ * N_; i += 1024) s.wr[i] = 0.f;
    __syncthreads();

    for (int t = 0; t < T_; t++) {
        float xz0 = 0.f, xz1 = 0.f, xz2 = 0.f, xz3 = 0.f;
        if (tid < 128) {
            const float* xzr = g_xz + (size_t)(b * T_ + t) * GATES_;
            int jg = k * 128 + tid;
            xz0 = xzr[jg]; xz1 = xzr[512 + jg]; xz2 = xzr[1024 + jg]; xz3 = xzr[1536 + jg];
        }

        // ==== P1: LSTM GEMM (tid<768) || out GEMM of t-1 (tid>=768) ====
        if (tid < 768) {
            const int g    = tid & 63;
            const int part = tid >> 6;
            const int gate = g >> 4;
            const int cg8  = (g & 15) * 8;
            const int colg = gate * 512 + k * 128 + cg8;
            float a0 = 0.f, a1 = 0.f, a2 = 0.f, a3 = 0.f;
            float a4 = 0.f, a5 = 0.f, a6 = 0.f, a7 = 0.f;
            const int r0 = part * 64;
            #pragma unroll 8
            for (int i = r0; i < r0 + 64; i++) {
                float sv = s.act[512 + i];
                uint4 wp = *reinterpret_cast<const uint4*>(&g_wlstm[(size_t)i * GATES_ + colg]);
                const __half2* h2 = reinterpret_cast<const __half2*>(&wp);
                float2 f0 = __half22float2(h2[0]);
                float2 f1 = __half22float2(h2[1]);
                float2 f2 = __half22float2(h2[2]);
                float2 f3 = __half22float2(h2[3]);
                a0 = fmaf(sv, f0.x, a0); a1 = fmaf(sv, f0.y, a1);
                a2 = fmaf(sv, f1.x, a2); a3 = fmaf(sv, f1.y, a3);
                a4 = fmaf(sv, f2.x, a4); a5 = fmaf(sv, f2.y, a5);
                a6 = fmaf(sv, f3.x, a6); a7 = fmaf(sv, f3.y, a7);
            }
            const int cl = gate * 128 + cg8;
            *reinterpret_cast<float4*>(&s.zbuf[part * 512 + cl])     = make_float4(a0, a1, a2, a3);
            *reinterpret_cast<float4*>(&s.zbuf[part * 512 + cl + 4]) = make_float4(a4, a5, a6, a7);
        } else if (t > 0) {
            const int q    = tid - 768;
            const int grp  = q & 15;
            const int part = q >> 4;
            const int cg8  = grp * 8;
            const int colg = k * 128 + cg8;
            float a0 = 0.f, a1 = 0.f, a2 = 0.f, a3 = 0.f;
            float a4 = 0.f, a5 = 0.f, a6 = 0.f, a7 = 0.f;
            const int r0 = part * 48;
            #pragma unroll 8
            for (int i = r0; i < r0 + 48; i++) {
                float sv = s.act[512 + i];
                uint4 wp = *reinterpret_cast<const uint4*>(&g_wo[(size_t)i * OUT_ + colg]);
                const __half2* h2 = reinterpret_cast<const __half2*>(&wp);
                float2 f0 = __half22float2(h2[0]);
                float2 f1 = __half22float2(h2[1]);
                float2 f2 = __half22float2(h2[2]);
                float2 f3 = __half22float2(h2[3]);
                a0 = fmaf(sv, f0.x, a0); a1 = fmaf(sv, f0.y, a1);
                a2 = fmaf(sv, f1.x, a2); a3 = fmaf(sv, f1.y, a3);
                a4 = fmaf(sv, f2.x, a4); a5 = fmaf(sv, f2.y, a5);
                a6 = fmaf(sv, f3.x, a6); a7 = fmaf(sv, f3.y, a7);
            }
            *reinterpret_cast<float4*>(&s.zbuf[6144 + part * 128 + cg8])     = make_float4(a0, a1, a2, a3);
            *reinterpret_cast<float4*>(&s.zbuf[6144 + part * 128 + cg8 + 4]) = make_float4(a4, a5, a6, a7);
        }
        __syncthreads();

        // ==== P2+P3 fused: gate reduce + LSTM pointwise (tid<128) || out reduce+store (512<=tid<640) ====
        if (tid < 128) {
            const int j  = tid;
            const int jg = k * 128 + j;
            float z0 = 0.f, z1 = 0.f, z2 = 0.f, z3 = 0.f;
            #pragma unroll
            for (int p = 0; p < 12; p++) {
                z0 += s.zbuf[p * 512 + j];
                z1 += s.zbuf[p * 512 + 128 + j];
                z2 += s.zbuf[p * 512 + 256 + j];
                z3 += s.zbuf[p * 512 + 384 + j];
            }
            float zi = z0 + xz0 + bl[jg];
            float zf = z1 + xz1 + bl[512 + jg];
            float zg = z2 + xz2 + bl[1024 + jg];
            float zo = z3 + xz3 + bl[1536 + jg];
            float cn = sigf(zf) * s.c[j] + sigf(zi) * tanhf(zg);
            s.c[j] = cn;
            s.act[768 + jg] = sigf(zo) * tanhf(cn);
        } else if (t > 0 && tid >= 512 && tid < 640) {
            const int o = tid - 512;
            float acc = bo[k * 128 + o];
            #pragma unroll
            for (int p = 0; p < 16; p++) acc += s.zbuf[6144 + p * 128 + o];
            out[(size_t)b * T_ * OUT_ + (size_t)(t - 1) * OUT_ + k * 128 + o] = acc;
        }
        cluster_sync();   // S1
        if (tid < 128) {
            #pragma unroll
            for (int p = 0; p < CL_; p++)
                if (p != k) s.act[768 + p * 128 + tid] = dsmem_ld(&s.act[768 + p * 128 + tid], p);
        }
        __syncthreads();

        // ==== P4: iface GEMM slice (fp16) ====
        if (tid < 960) {
            const int grp  = tid % 15;
            const int part = tid / 15;
            const int cg8  = grp * 8;
            float a0 = 0.f, a1 = 0.f, a2 = 0.f, a3 = 0.f;
            float a4 = 0.f, a5 = 0.f, a6 = 0.f, a7 = 0.f;
            const int r0 = part * 8;
            #pragma unroll
            for (int i = r0; i < r0 + 8; i++) {
                float sv = s.act[768 + i];
                uint4 wp = *reinterpret_cast<const uint4*>(&g_wif[(size_t)i * 480 + k * 120 + cg8]);
                const __half2* h2 = reinterpret_cast<const __half2*>(&wp);
                float2 f0 = __half22float2(h2[0]);
                float2 f1 = __half22float2(h2[1]);
                float2 f2 = __half22float2(h2[2]);
                float2 f3 = __half22float2(h2[3]);
                a0 = fmaf(sv, f0.x, a0); a1 = fmaf(sv, f0.y, a1);
                a2 = fmaf(sv, f1.x, a2); a3 = fmaf(sv, f1.y, a3);
                a4 = fmaf(sv, f2.x, a4); a5 = fmaf(sv, f2.y, a5);
                a6 = fmaf(sv, f3.x, a6); a7 = fmaf(sv, f3.y, a7);
            }
            *reinterpret_cast<float4*>(&s.zbuf[part * 120 + cg8])     = make_float4(a0, a1, a2, a3);
            *reinterpret_cast<float4*>(&s.zbuf[part * 120 + cg8 + 4]) = make_float4(a4, a5, a6, a7);
        }
        __syncthreads();
        {
            const int base  = k * 118;
            const int ncols = (k < 3) ? 118 : 117;
            if (tid < ncols) {
                float acc = 0.f;
                #pragma unroll 8
                for (int p = 0; p < 64; p++) acc += s.zbuf[p * 120 + tid];
                s.v[base + tid] = acc + bif[base + tid];
            }
        }
        cluster_sync();   // S2
        if (tid < IFACE_) {
            const int owner = tid / 118;
            if (owner != k) s.v[tid] = dsmem_ld(&s.v[tid], owner);
        }
        __syncthreads();

        // ==== X1 ====
        if (tid < 128) {
            float f0 = sigf(s.v[453]), f1 = sigf(s.v[454]), f2 = sigf(s.v[455]), f3 = sigf(s.v[456]);
            float ret = (1.f - f0 * s.wr[tid]) * (1.f - f1 * s.wr[128 + tid])
                      * (1.f - f2 * s.wr[256 + tid]) * (1.f - f3 * s.wr[384 + tid]);
            float u = s.usage[tid], w0 = s.ww[tid];
            s.usage[tid] = (u + w0 - u * w0) * ret;
        } else if (tid < 256) {
            int n = tid - 128;
            const float4* mr = reinterpret_cast<const float4*>(&s.M[n * MS_]);
            const float4* kr = reinterpret_cast<const float4*>(&s.v[260]);
            float d = 0.f;
            #pragma unroll
            for (int q = 0; q < 16; q++) d += dot4(mr[q], kr[q]);
            s.cw[n] = d / (s.Mnorm[n] + EPS_);
        } else if (wi >= 8 && wi < 12) {
            int r = wi - 8;
            float kv = s.v[r * 64 + lane], kv2 = s.v[r * 64 + lane + 32];
            float ssum = warp_sum(kv * kv + kv2 * kv2);
            if (lane == 0) s.keynorm[r] = sqrtf(ssum);
        } else if (wi == 12) {
            float kv = s.v[260 + lane], kv2 = s.v[260 + lane + 32];
            float ssum = warp_sum(kv * kv + kv2 * kv2);
            if (lane == 0) s.sc[3] = sqrtf(ssum);
        } else if (tid >= 416 && tid < 480) {
            int w = tid - 416;
            s.erasev[w] = sigf(s.v[325 + w]);
            s.wvec[w]   = s.v[389 + w];
        } else if (tid >= 480 && tid < 484) {
            int r = tid - 480;
            float m0 = s.v[459 + 3 * r], m1 = s.v[460 + 3 * r], m2 = s.v[461 + 3 * r];
            float mx = fmaxf(m0, fmaxf(m1, m2));
            float e0 = expf(m0 - mx), e1 = expf(m1 - mx), e2 = expf(m2 - mx);
            float ssum = e0 + e1 + e2;
            s.modes[3 * r] = e0 / ssum; s.modes[3 * r + 1] = e1 / ssum; s.modes[3 * r + 2] = e2 / ssum;
        } else if (tid >= 484 && tid < 488) {
            int r = tid - 484;
            s.rb[r] = 1.f + softplusf(s.v[256 + r]);
        } else if (tid == 488) s.sc[0] = 1.f + softplusf(s.v[324]);
        else if (tid == 489) s.sc[1] = sigf(s.v[457]);
        else if (tid == 490) s.sc[2] = sigf(s.v[458]);
        __syncthreads();

        // ==== X2 ====
        if (wi == 0) {
            float tsc = s.sc[0] / (s.sc[3] + EPS_);
            float a0 = s.cw[lane] * tsc,      a1 = s.cw[lane + 32] * tsc;
            float a2 = s.cw[lane + 64] * tsc, a3 = s.cw[lane + 96] * tsc;
            float mx = warp_max(fmaxf(fmaxf(a0, a1), fmaxf(a2, a3)));
            float e0 = expf(a0 - mx), e1 = expf(a1 - mx), e2 = expf(a2 - mx), e3 = expf(a3 - mx);
            float su = warp_sum(e0 + e1 + e2 + e3);
            float inv = 1.f / su;
            s.cw[lane] = e0 * inv; s.cw[lane + 32] = e1 * inv;
            s.cw[lane + 64] = e2 * inv; s.cw[lane + 96] = e3 * inv;
        } else if (tid >= 128 && tid < 256) {
            int e = tid - 128;
            float ue = s.usage[e];
            int cnt = 0;
            #pragma unroll 8
            for (int j = 0; j < 128; j++) {
                float uj = s.usage[j];
                cnt += (uj < ue) || (uj == ue && j < e);
            }
            s.skv[cnt] = ue; s.ski[cnt] = e;
        }
        __syncthreads();

        // ==== X3+X4 ====
        if (wi == 0) {
            float running = 1.f;
            #pragma unroll
            for (int r = 0; r < 4; r++) {
                float v0 = s.skv[r * 32 + lane];
                int   ix = s.ski[r * 32 + lane];
                float c = v0;
                #pragma unroll
                for (int off = 1; off < 32; off <<= 1) {
                    float tsh = __shfl_up_sync(0xffffffffu, c, off);
                    if (lane >= off) c *= tsh;
                }
                float excl_in = __shfl_up_sync(0xffffffffu, c, 1);
                float excl = (lane == 0) ? running : excl_in * running;
                s.aalloc[ix] = (1.f - v0) * excl;
                running *= __shfl_sync(0xffffffffu, c, 31);
            }
            __syncwarp();
            float ag = s.sc[1], wg = s.sc[2];
            #pragma unroll
            for (int o = 0; o < 4; o++) {
                int n = lane + o * 32;
                s.ww[n] = wg * (ag * s.aalloc[n] + (1.f - ag) * s.cw[n]);
            }
        }
        __syncthreads();

        // ==== X5+X6 ====
        {
            const int ti = (tid >> 5) * 4;
            const int tj = (tid & 31) * 4;
            float wwi[4], nv[4][4];
            #pragma unroll
            for (int r = 0; r < 4; r++) wwi[r] = s.ww[ti + r];
            float4 wwj4 = *reinterpret_cast<const float4*>(&s.ww[tj]);
            float4 pj4  = *reinterpret_cast<const float4*>(&s.prec[tj]);
            #pragma unroll
            for (int r = 0; r < 4; r++) {
                float4 lo = *reinterpret_cast<const float4*>(&s.link[(ti + r) * LINKS_ + tj]);
                nv[r][0] = (1.f - wwi[r] - wwj4.x) * lo.x + wwi[r] * pj4.x;
                nv[r][1] = (1.f - wwi[r] - wwj4.y) * lo.y + wwi[r] * pj4.y;
                nv[r][2] = (1.f - wwi[r] - wwj4.z) * lo.z + wwi[r] * pj4.z;
                nv[r][3] = (1.f - wwi[r] - wwj4.w) * lo.w + wwi[r] * pj4.w;
                #pragma unroll
                for (int cc = 0; cc < 4; cc++)
                    if (ti + r == tj + cc) nv[r][cc] = 0.f;
                *reinterpret_cast<float4*>(&s.link[(ti + r) * LINKS_ + tj]) =
                    make_float4(nv[r][0], nv[r][1], nv[r][2], nv[r][3]);
            }
            #pragma unroll
            for (int cc = 0; cc < 4; cc++)
                *reinterpret_cast<float4*>(&s.linkT[(tj + cc) * LINKS_ + ti]) =
                    make_float4(nv[0][cc], nv[1][cc], nv[2][cc], nv[3][cc]);
        }
        if (tid < 512) {
            const int row = tid >> 2, sub = tid & 3;
            const int w0 = sub * 16;
            float wwn = s.ww[row];
            float sq = 0.f;
            #pragma unroll
            for (int q = 0; q < 4; q++) {
                float4 m  = *reinterpret_cast<const float4*>(&s.M[row * MS_ + w0 + q * 4]);
                float4 ev = *reinterpret_cast<const float4*>(&s.erasev[w0 + q * 4]);
                float4 wv = *reinterpret_cast<const float4*>(&s.wvec[w0 + q * 4]);
                m.x = m.x * (1.f - wwn * ev.x) + wwn * wv.x;
                m.y = m.y * (1.f - wwn * ev.y) + wwn * wv.y;
                m.z = m.z * (1.f - wwn * ev.z) + wwn * wv.z;
                m.w = m.w * (1.f - wwn * ev.w) + wwn * wv.w;
                sq += m.x * m.x + m.y * m.y + m.z * m.z + m.w * m.w;
                *reinterpret_cast<float4*>(&s.M[row * MS_ + w0 + q * 4]) = m;
            }
            sq += __shfl_xor_sync(0xffffffffu, sq, 1);
            sq += __shfl_xor_sync(0xffffffffu, sq, 2);
            if (sub == 0) s.Mnorm[row] = sqrtf(sq);
        } else if (wi == 16) {
            float ssum = warp_sum(s.ww[lane] + s.ww[lane + 32] + s.ww[lane + 64] + s.ww[lane + 96]);
            if (lane == 0) s.sc[4] = ssum;
        }
        __syncthreads();

        // ==== X7+X8: fw + crs(q=0..7) on tid<512; bw + crs(q=8..15) on tid>=512 ====
        if (tid < 512) {
            const int r = tid >> 7, i = tid & 127;
            const float4* lr  = reinterpret_cast<const float4*>(&s.link[i * LINKS_]);
            const float4* wrr = reinterpret_cast<const float4*>(&s.wr[r * 128]);
            float acc = 0.f;
            #pragma unroll
            for (int q = 0; q < 32; q++) acc += dot4(lr[q], wrr[q]);
            s.fw[tid] = acc;
            const float4* mr = reinterpret_cast<const float4*>(&s.M[i * MS_]);
            const float4* kr = reinterpret_cast<const float4*>(&s.v[r * 64]);
            float d = 0.f;
            #pragma unroll
            for (int q = 0; q < 8; q++) d += dot4(mr[q], kr[q]);
            float scale = s.rb[r] / ((s.Mnorm[i] + EPS_) * (s.keynorm[r] + EPS_));
            s.crs[tid] = scale * d;
        } else {
            const int q2 = tid - 512;
            const int r = q2 >> 7, i = q2 & 127;
            const float4* lr  = reinterpret_cast<const float4*>(&s.linkT[i * LINKS_]);
            const float4* wrr = reinterpret_cast<const float4*>(&s.wr[r * 128]);
            float acc = 0.f;
            #pragma unroll
            for (int q = 0; q < 32; q++) acc += dot4(lr[q], wrr[q]);
            s.bw[q2] = acc;
            const float4* mr = reinterpret_cast<const float4*>(&s.M[i * MS_]);
            const float4* kr = reinterpret_cast<const float4*>(&s.v[r * 64]);
            float d = 0.f;
            #pragma unroll
            for (int q = 8; q < 16; q++) d += dot4(mr[q], kr[q]);
            float scale = s.rb[r] / ((s.Mnorm[i] + EPS_) * (s.keynorm[r] + EPS_));
            s.crsb[q2] = scale * d;
        }
        __syncthreads();

        // ==== X9+X10: per-r read softmax + wr write (warps 0-3) || prec update (warp 4) ====
        if (wi < 4) {
            int r = wi;
            float a0 = s.crs[r * N_ + lane]      + s.crsb[r * N_ + lane];
            float a1 = s.crs[r * N_ + lane + 32] + s.crsb[r * N_ + lane + 32];
            float a2 = s.crs[r * N_ + lane + 64] + s.crsb[r * N_ + lane + 64];
            float a3 = s.crs[r * N_ + lane + 96] + s.crsb[r * N_ + lane + 96];
            float mx = warp_max(fmaxf(fmaxf(a0, a1), fmaxf(a2, a3)));
            float e0 = expf(a0 - mx), e1 = expf(a1 - mx), e2 = expf(a2 - mx), e3 = expf(a3 - mx);
            float su = warp_sum(e0 + e1 + e2 + e3);
            float inv = 1.f / su;
            float m0 = s.modes[3 * r], m1 = s.modes[3 * r + 1], m2 = s.modes[3 * r + 2];
            #pragma unroll
            for (int o = 0; o < 4; o++) {
                int n = lane + o * 32;
                float cv = (o == 0 ? e0 : o == 1 ? e1 : o == 2 ? e2 : e3) * inv;
                s.wr[r * 128 + n] = m0 * s.bw[r * 128 + n] + m1 * cv + m2 * s.fw[r * 128 + n];
            }
        } else if (wi == 4) {
            float ssum = s.sc[4];
            #pragma unroll
            for (int o = 0; o < 4; o++) {
                int n = lane + o * 32;
                s.prec[n] = (1.f - ssum) * s.prec[n] + s.ww[n];
            }
        }
        __syncthreads();

        // ==== X11: reads_n = wr_n @ M ====
        {
            int outi = tid & 255;
            int chunk = tid >> 8;
            int r = outi >> 6, w = outi & 63;
            float acc = 0.f;
            int n0 = chunk * 32;
            #pragma unroll 4
            for (int n = n0; n < n0 + 32; n++)
                acc = fmaf(s.wr[r * 128 + n], s.M[n * MS_ + w], acc);
            s.zbuf[chunk * 256 + outi] = acc;
        }
        __syncthreads();
        if (tid < 256)
            s.act[512 + tid] = s.zbuf[tid] + s.zbuf[256 + tid] + s.zbuf[512 + tid] + s.zbuf[768 + tid];
        __syncthreads();
    }

    // ==== final out GEMM for t = T-1 ====
    {
        const int grp  = tid & 15;
        const int part = tid >> 4;
        const int cg8  = grp * 8;
        const int colg = k * 128 + cg8;
        float a0 = 0.f, a1 = 0.f, a2 = 0.f, a3 = 0.f;
        float a4 = 0.f, a5 = 0.f, a6 = 0.f, a7 = 0.f;
        const int r0 = part * 12;
        #pragma unroll
        for (int i = r0; i < r0 + 12; i++) {
            float sv = s.act[512 + i];
            uint4 wp = *reinterpret_cast<const uint4*>(&g_wo[(size_t)i * OUT_ + colg]);
            const __half2* h2 = reinterpret_cast<const __half2*>(&wp);
            float2 f0 = __half22float2(h2[0]);
            float2 f1 = __half22float2(h2[1]);
            float2 f2 = __half22float2(h2[2]);
            float2 f3 = __half22float2(h2[3]);
            a0 = fmaf(sv, f0.x, a0); a1 = fmaf(sv, f0.y, a1);
            a2 = fmaf(sv, f1.x, a2); a3 = fmaf(sv, f1.y, a3);
            a4 = fmaf(sv, f2.x, a4); a5 = fmaf(sv, f2.y, a5);
            a6 = fmaf(sv, f3.x, a6); a7 = fmaf(sv, f3.y, a7);
        }
        *reinterpret_cast<float4*>(&s.zbuf[part * 128 + cg8])     = make_float4(a0, a1, a2, a3);
        *reinterpret_cast<float4*>(&s.zbuf[part * 128 + cg8 + 4]) = make_float4(a4, a5, a6, a7);
    }
    __syncthreads();
    if (tid < 128) {
        float acc = bo[k * 128 + tid];
        #pragma unroll
        for (int p = 0; p < 64; p++) acc += s.zbuf[p * 128 + tid];
        out[(size_t)b * T_ * OUT_ + (size_t)(T_ - 1) * OUT_ + k * 128 + tid] = acc;
    }
}

extern "C" void kernel_launch(void* const* d_in, const int* in_sizes, int n_in,
                              void* d_out, int out_size) {
    (void)in_sizes; (void)n_in; (void)out_size;
    const float* x   = (const float*)d_in[0];
    const float* Wx  = (const float*)d_in[1];
    const float* Wh  = (const float*)d_in[2];
    const float* bl  = (const float*)d_in[3];
    const float* Wif = (const float*)d_in[4];
    const float* bif = (const float*)d_in[5];
    const float* Wo  = (const float*)d_in[6];
    const float* bo  = (const float*)d_in[7];
    float* out = (float*)d_out;

    cvt_lstm<<<(768 * GATES_ / 2 + 1023) / 1024, 1024>>>(Wx, Wh);
    cvt_wo<<<(768 * OUT_ / 2 + 1023) / 1024, 1024>>>(Wo);
    cvt_wif<<<(512 * 480 + 1023) / 1024, 1024>>>(Wif);

    dim3 pg(B_ * T_ / 128, GATES_ / 128);
    xz_kernel<<<pg, 256>>>(x, Wx);

    cudaFuncSetAttribute(dnc_kernel, cudaFuncAttributeMaxDynamicSharedMemorySize,
                         (int)sizeof(Smem));
    dnc_kernel<<<B_ * CL_, 1024, sizeof(Smem)>>>(bl, bif, bo, out);
}

// round 15
// speedup vs baseline: 1.7882x; 1.0910x over previous
#include <cuda_runtime.h>
#include <cuda_fp16.h>
#include <stdint.h>
#include <math.h>

#define B_      32
#define T_      128
#define IN_     512
#define OUT_    512
#define N_      128
#define WD_     64
#define R_      4
#define H_      512
#define IFACE_  471
#define GATES_  2048
#define EPS_    1e-6f
#define LINKS_  132
#define MS_     68
#define CL_     4

__device__ float  g_xz[B_ * T_ * GATES_];     // precomputed x_t @ Wx[0:512,:]
__device__ __half g_wlstm[768 * GATES_];      // rows 0-255: Wx rows 512-767; rows 256-767: Wh
__device__ __half g_wo[768 * OUT_];           // Wo in fp16
__device__ __half g_wif[512 * 480];           // Wif fp16, per-rank 120-col padded slices

struct Smem {
    float M[N_ * MS_];
    float link[N_ * LINKS_];
    float linkT[N_ * LINKS_];
    float act[1280];            // [512:768) reads | [768:1280) h
    float c[128];
    float zbuf[8192];
    float v[472];
    float usage[N_];
    float prec[N_];
    float ww[N_];
    float wr[R_ * N_];
    float Mnorm[N_];
    float skv[N_];
    int   ski[N_];
    float aalloc[N_];
    float cw[N_];
    float crs[R_ * N_];
    float fw[R_ * N_];
    float bw[R_ * N_];
    float erasev[WD_];
    float wvec[WD_];
    float rb[R_];
    float keynorm[R_];
    float modes[R_ * 3];
    float sc[8];
};

__device__ __forceinline__ float sigf(float x) { return 1.f / (1.f + expf(-x)); }
__device__ __forceinline__ float softplusf(float x) {
    return fmaxf(x, 0.f) + log1pf(expf(-fabsf(x)));
}
__device__ __forceinline__ float warp_sum(float v) {
    #pragma unroll
    for (int o = 16; o; o >>= 1) v += __shfl_xor_sync(0xffffffffu, v, o);
    return v;
}
__device__ __forceinline__ float warp_max(float v) {
    #pragma unroll
    for (int o = 16; o; o >>= 1) v = fmaxf(v, __shfl_xor_sync(0xffffffffu, v, o));
    return v;
}
__device__ __forceinline__ void cluster_sync() {
    asm volatile("barrier.cluster.arrive.aligned;" ::: "memory");
    asm volatile("barrier.cluster.wait.aligned;" ::: "memory");
}
__device__ __forceinline__ float dsmem_ld(const float* p, int rank) {
    uint32_t la = (uint32_t)__cvta_generic_to_shared((void*)p);
    uint32_t ra;
    asm("mapa.shared::cluster.u32 %0, %1, %2;" : "=r"(ra) : "r"(la), "r"(rank));
    float val;
    asm volatile("ld.shared::cluster.f32 %0, [%1];" : "=f"(val) : "r"(ra));
    return val;
}
__device__ __forceinline__ float dot4(float4 a, float4 b) {
    return fmaf(a.x, b.x, fmaf(a.y, b.y, fmaf(a.z, b.z, a.w * b.w)));
}

// ---------------- weight conversion kernels ----------------
__global__ void __launch_bounds__(1024) cvt_lstm(const float* __restrict__ Wx,
                                                 const float* __restrict__ Wh) {
    int idx2 = (blockIdx.x * 1024 + threadIdx.x) * 2;
    if (idx2 >= 768 * GATES_) return;
    int row = idx2 >> 11, col = idx2 & 2047;
    const float* src = (row < 256) ? (Wx + (size_t)(512 + row) * GATES_ + col)
                                   : (Wh + (size_t)(row - 256) * GATES_ + col);
    *reinterpret_cast<__half2*>(&g_wlstm[idx2]) = __floats2half2_rn(src[0], src[1]);
}
__global__ void __launch_bounds__(1024) cvt_wo(const float* __restrict__ Wo) {
    int idx2 = (blockIdx.x * 1024 + threadIdx.x) * 2;
    if (idx2 >= 768 * OUT_) return;
    *reinterpret_cast<__half2*>(&g_wo[idx2]) = __floats2half2_rn(Wo[idx2], Wo[idx2 + 1]);
}
__global__ void __launch_bounds__(1024) cvt_wif(const float* __restrict__ Wif) {
    int idx = blockIdx.x * 1024 + threadIdx.x;
    if (idx >= 512 * 480) return;
    int row = idx / 480, c = idx % 480;
    int rank = c / 120, cc = c % 120;
    int ncols = (rank < 3) ? 118 : 117;
    float val = (cc < ncols) ? Wif[(size_t)row * IFACE_ + rank * 118 + cc] : 0.f;
    g_wif[idx] = __float2half_rn(val);
}

// ---------------- precompute kernel: g_xz = x @ Wx[0:512,:] ----------------
__global__ void __launch_bounds__(256) xz_kernel(const float* __restrict__ x,
                                                 const float* __restrict__ Wx) {
    __shared__ float xsT[16][132];
    __shared__ float ws[16][132];
    const int rb = blockIdx.x * 128;
    const int cb = blockIdx.y * 128;
    const int tid = threadIdx.x;
    const int tr0 = (tid >> 4) * 4;
    const int tc0 = (tid & 15) * 4;

    float acc[8][8];
    #pragma unroll
    for (int i = 0; i < 8; i++)
        #pragma unroll
        for (int j = 0; j < 8; j++) acc[i][j] = 0.f;

    for (int kt = 0; kt < IN_; kt += 16) {
        #pragma unroll
        for (int l = 0; l < 2; l++) {
            int idx = tid + l * 256;
            int row = idx >> 2;
            int k4  = (idx & 3) * 4;
            float4 xv = *reinterpret_cast<const float4*>(&x[(size_t)(rb + row) * IN_ + kt + k4]);
            xsT[k4 + 0][row] = xv.x; xsT[k4 + 1][row] = xv.y;
            xsT[k4 + 2][row] = xv.z; xsT[k4 + 3][row] = xv.w;
        }
        #pragma unroll
        for (int l = 0; l < 2; l++) {
            int idx = tid + l * 256;
            int kk = idx >> 5;
            int c4 = (idx & 31) * 4;
            *reinterpret_cast<float4*>(&ws[kk][c4]) =
                *reinterpret_cast<const float4*>(&Wx[(size_t)(kt + kk) * GATES_ + cb + c4]);
        }
        __syncthreads();
        #pragma unroll
        for (int kk = 0; kk < 16; kk++) {
            float xr[8], wc[8];
            *reinterpret_cast<float4*>(&xr[0]) = *reinterpret_cast<float4*>(&xsT[kk][tr0]);
            *reinterpret_cast<float4*>(&xr[4]) = *reinterpret_cast<float4*>(&xsT[kk][tr0 + 64]);
            *reinterpret_cast<float4*>(&wc[0]) = *reinterpret_cast<float4*>(&ws[kk][tc0]);
            *reinterpret_cast<float4*>(&wc[4]) = *reinterpret_cast<float4*>(&ws[kk][tc0 + 64]);
            #pragma unroll
            for (int i = 0; i < 8; i++)
                #pragma unroll
                for (int j = 0; j < 8; j++)
                    acc[i][j] = fmaf(xr[i], wc[j], acc[i][j]);
        }
        __syncthreads();
    }
    #pragma unroll
    for (int i = 0; i < 8; i++) {
        int row = rb + ((i < 4) ? (tr0 + i) : (64 + tr0 + i - 4));
        float4* d0 = reinterpret_cast<float4*>(&g_xz[(size_t)row * GATES_ + cb + tc0]);
        float4* d1 = reinterpret_cast<float4*>(&g_xz[(size_t)row * GATES_ + cb + 64 + tc0]);
        *d0 = make_float4(acc[i][0], acc[i][1], acc[i][2], acc[i][3]);
        *d1 = make_float4(acc[i][4], acc[i][5], acc[i][6], acc[i][7]);
    }
}

// ---------------- main recurrent kernel ----------------
__global__ void __launch_bounds__(1024, 1) __cluster_dims__(CL_, 1, 1) dnc_kernel(
    const float* __restrict__ bl,
    const float* __restrict__ bif,
    const float* __restrict__ bo,
    float* __restrict__ out)
{
    extern __shared__ char smraw[];
    Smem& s = *reinterpret_cast<Smem*>(smraw);
    const int tid  = threadIdx.x;
    const int lane = tid & 31;
    const int wi   = tid >> 5;
    uint32_t krank_u;
    asm("mov.u32 %0, %%cluster_ctarank;" : "=r"(krank_u));
    const int k = (int)krank_u;
    const int b = blockIdx.x >> 2;

    for (int i = tid; i < N_ * MS_;    i += 1024) s.M[i]     = 0.f;
    for (int i = tid; i < N_ * LINKS_; i += 1024) { s.link[i] = 0.f; s.linkT[i] = 0.f; }
    for (int i = tid; i < 1280;        i += 1024) s.act[i]   = 0.f;
    if (tid < 128) s.c[tid] = 0.f;
    if (tid < N_) { s.usage[tid] = 0.f; s.prec[tid] = 0.f; s.ww[tid] = 0.f; s.Mnorm[tid] = 0.f; }
    for (int i = tid; i < R_ * N_; i += 1024) s.wr[i] = 0.f;
    __syncthreads();

    for (int t = 0; t < T_; t++) {
        float xz0 = 0.f, xz1 = 0.f, xz2 = 0.f, xz3 = 0.f;
        if (tid < 128) {
            const float* xzr = g_xz + (size_t)(b * T_ + t) * GATES_;
            int jg = k * 128 + tid;
            xz0 = xzr[jg]; xz1 = xzr[512 + jg]; xz2 = xzr[1024 + jg]; xz3 = xzr[1536 + jg];
        }

        // ==== P1: LSTM GEMM (tid<768) || out GEMM of t-1 (tid>=768) ====
        if (tid < 768) {
            const int g    = tid & 63;
            const int part = tid >> 6;
            const int gate = g >> 4;
            const int cg8  = (g & 15) * 8;
            const int colg = gate * 512 + k * 128 + cg8;
            float a0 = 0.f, a1 = 0.f, a2 = 0.f, a3 = 0.f;
            float a4 = 0.f, a5 = 0.f, a6 = 0.f, a7 = 0.f;
            const int r0 = part * 64;
            #pragma unroll 8
            for (int i = r0; i < r0 + 64; i++) {
                float sv = s.act[512 + i];
                uint4 wp = *reinterpret_cast<const uint4*>(&g_wlstm[(size_t)i * GATES_ + colg]);
                const __half2* h2 = reinterpret_cast<const __half2*>(&wp);
                float2 f0 = __half22float2(h2[0]);
                float2 f1 = __half22float2(h2[1]);
                float2 f2 = __half22float2(h2[2]);
                float2 f3 = __half22float2(h2[3]);
                a0 = fmaf(sv, f0.x, a0); a1 = fmaf(sv, f0.y, a1);
                a2 = fmaf(sv, f1.x, a2); a3 = fmaf(sv, f1.y, a3);
                a4 = fmaf(sv, f2.x, a4); a5 = fmaf(sv, f2.y, a5);
                a6 = fmaf(sv, f3.x, a6); a7 = fmaf(sv, f3.y, a7);
            }
            const int cl = gate * 128 + cg8;
            *reinterpret_cast<float4*>(&s.zbuf[part * 512 + cl])     = make_float4(a0, a1, a2, a3);
            *reinterpret_cast<float4*>(&s.zbuf[part * 512 + cl + 4]) = make_float4(a4, a5, a6, a7);
        } else if (t > 0) {
            const int q    = tid - 768;
            const int grp  = q & 15;
            const int part = q >> 4;
            const int cg8  = grp * 8;
            const int colg = k * 128 + cg8;
            float a0 = 0.f, a1 = 0.f, a2 = 0.f, a3 = 0.f;
            float a4 = 0.f, a5 = 0.f, a6 = 0.f, a7 = 0.f;
            const int r0 = part * 48;
            #pragma unroll 8
            for (int i = r0; i < r0 + 48; i++) {
                float sv = s.act[512 + i];
                uint4 wp = *reinterpret_cast<const uint4*>(&g_wo[(size_t)i * OUT_ + colg]);
                const __half2* h2 = reinterpret_cast<const __half2*>(&wp);
                float2 f0 = __half22float2(h2[0]);
                float2 f1 = __half22float2(h2[1]);
                float2 f2 = __half22float2(h2[2]);
                float2 f3 = __half22float2(h2[3]);
                a0 = fmaf(sv, f0.x, a0); a1 = fmaf(sv, f0.y, a1);
                a2 = fmaf(sv, f1.x, a2); a3 = fmaf(sv, f1.y, a3);
                a4 = fmaf(sv, f2.x, a4); a5 = fmaf(sv, f2.y, a5);
                a6 = fmaf(sv, f3.x, a6); a7 = fmaf(sv, f3.y, a7);
            }
            *reinterpret_cast<float4*>(&s.zbuf[6144 + part * 128 + cg8])     = make_float4(a0, a1, a2, a3);
            *reinterpret_cast<float4*>(&s.zbuf[6144 + part * 128 + cg8 + 4]) = make_float4(a4, a5, a6, a7);
        }
        __syncthreads();

        // ==== P2+P3 fused: gate reduce + LSTM pointwise (tid<128) || out reduce+store ====
        if (tid < 128) {
            const int j  = tid;
            const int jg = k * 128 + j;
            float z0 = 0.f, z1 = 0.f, z2 = 0.f, z3 = 0.f;
            #pragma unroll
            for (int p = 0; p < 12; p++) {
                z0 += s.zbuf[p * 512 + j];
                z1 += s.zbuf[p * 512 + 128 + j];
                z2 += s.zbuf[p * 512 + 256 + j];
                z3 += s.zbuf[p * 512 + 384 + j];
            }
            float zi = z0 + xz0 + bl[jg];
            float zf = z1 + xz1 + bl[512 + jg];
            float zg = z2 + xz2 + bl[1024 + jg];
            float zo = z3 + xz3 + bl[1536 + jg];
            float cn = sigf(zf) * s.c[j] + sigf(zi) * tanhf(zg);
            s.c[j] = cn;
            s.act[768 + jg] = sigf(zo) * tanhf(cn);
        } else if (t > 0 && tid >= 512 && tid < 640) {
            const int o = tid - 512;
            float acc = bo[k * 128 + o];
            #pragma unroll
            for (int p = 0; p < 16; p++) acc += s.zbuf[6144 + p * 128 + o];
            out[(size_t)b * T_ * OUT_ + (size_t)(t - 1) * OUT_ + k * 128 + o] = acc;
        }
        cluster_sync();   // S1
        if (tid < 128) {
            #pragma unroll
            for (int p = 0; p < CL_; p++)
                if (p != k) s.act[768 + p * 128 + tid] = dsmem_ld(&s.act[768 + p * 128 + tid], p);
        }
        __syncthreads();

        // ==== P4: iface GEMM slice (fp16) ====
        if (tid < 960) {
            const int grp  = tid % 15;
            const int part = tid / 15;
            const int cg8  = grp * 8;
            float a0 = 0.f, a1 = 0.f, a2 = 0.f, a3 = 0.f;
            float a4 = 0.f, a5 = 0.f, a6 = 0.f, a7 = 0.f;
            const int r0 = part * 8;
            #pragma unroll
            for (int i = r0; i < r0 + 8; i++) {
                float sv = s.act[768 + i];
                uint4 wp = *reinterpret_cast<const uint4*>(&g_wif[(size_t)i * 480 + k * 120 + cg8]);
                const __half2* h2 = reinterpret_cast<const __half2*>(&wp);
                float2 f0 = __half22float2(h2[0]);
                float2 f1 = __half22float2(h2[1]);
                float2 f2 = __half22float2(h2[2]);
                float2 f3 = __half22float2(h2[3]);
                a0 = fmaf(sv, f0.x, a0); a1 = fmaf(sv, f0.y, a1);
                a2 = fmaf(sv, f1.x, a2); a3 = fmaf(sv, f1.y, a3);
                a4 = fmaf(sv, f2.x, a4); a5 = fmaf(sv, f2.y, a5);
                a6 = fmaf(sv, f3.x, a6); a7 = fmaf(sv, f3.y, a7);
            }
            *reinterpret_cast<float4*>(&s.zbuf[part * 120 + cg8])     = make_float4(a0, a1, a2, a3);
            *reinterpret_cast<float4*>(&s.zbuf[part * 120 + cg8 + 4]) = make_float4(a4, a5, a6, a7);
        }
        __syncthreads();
        {
            const int base  = k * 118;
            const int ncols = (k < 3) ? 118 : 117;
            if (tid < ncols) {
                float acc = 0.f;
                #pragma unroll 8
                for (int p = 0; p < 64; p++) acc += s.zbuf[p * 120 + tid];
                s.v[base + tid] = acc + bif[base + tid];
            }
        }
        cluster_sync();   // S2
        if (tid < IFACE_) {
            const int owner = tid / 118;
            if (owner != k) s.v[tid] = dsmem_ld(&s.v[tid], owner);
        }
        __syncthreads();

        // ==== X1 ====
        if (tid < 128) {
            float f0 = sigf(s.v[453]), f1 = sigf(s.v[454]), f2 = sigf(s.v[455]), f3 = sigf(s.v[456]);
            float ret = (1.f - f0 * s.wr[tid]) * (1.f - f1 * s.wr[128 + tid])
                      * (1.f - f2 * s.wr[256 + tid]) * (1.f - f3 * s.wr[384 + tid]);
            float u = s.usage[tid], w0 = s.ww[tid];
            s.usage[tid] = (u + w0 - u * w0) * ret;
        } else if (tid < 256) {
            int n = tid - 128;
            const float4* mr = reinterpret_cast<const float4*>(&s.M[n * MS_]);
            const float4* kr = reinterpret_cast<const float4*>(&s.v[260]);
            float d = 0.f;
            #pragma unroll
            for (int q = 0; q < 16; q++) d += dot4(mr[q], kr[q]);
            s.cw[n] = d / (s.Mnorm[n] + EPS_);
        } else if (wi >= 8 && wi < 12) {
            int r = wi - 8;
            float kv = s.v[r * 64 + lane], kv2 = s.v[r * 64 + lane + 32];
            float ssum = warp_sum(kv * kv + kv2 * kv2);
            if (lane == 0) s.keynorm[r] = sqrtf(ssum);
        } else if (wi == 12) {
            float kv = s.v[260 + lane], kv2 = s.v[260 + lane + 32];
            float ssum = warp_sum(kv * kv + kv2 * kv2);
            if (lane == 0) s.sc[3] = sqrtf(ssum);
        } else if (tid >= 416 && tid < 480) {
            int w = tid - 416;
            s.erasev[w] = sigf(s.v[325 + w]);
            s.wvec[w]   = s.v[389 + w];
        } else if (tid >= 480 && tid < 484) {
            int r = tid - 480;
            float m0 = s.v[459 + 3 * r], m1 = s.v[460 + 3 * r], m2 = s.v[461 + 3 * r];
            float mx = fmaxf(m0, fmaxf(m1, m2));
            float e0 = expf(m0 - mx), e1 = expf(m1 - mx), e2 = expf(m2 - mx);
            float ssum = e0 + e1 + e2;
            s.modes[3 * r] = e0 / ssum; s.modes[3 * r + 1] = e1 / ssum; s.modes[3 * r + 2] = e2 / ssum;
        } else if (tid >= 484 && tid < 488) {
            int r = tid - 484;
            s.rb[r] = 1.f + softplusf(s.v[256 + r]);
        } else if (tid == 488) s.sc[0] = 1.f + softplusf(s.v[324]);
        else if (tid == 489) s.sc[1] = sigf(s.v[457]);
        else if (tid == 490) s.sc[2] = sigf(s.v[458]);
        __syncthreads();

        // ==== X2 ====
        if (wi == 0) {
            float tsc = s.sc[0] / (s.sc[3] + EPS_);
            float a0 = s.cw[lane] * tsc,      a1 = s.cw[lane + 32] * tsc;
            float a2 = s.cw[lane + 64] * tsc, a3 = s.cw[lane + 96] * tsc;
            float mx = warp_max(fmaxf(fmaxf(a0, a1), fmaxf(a2, a3)));
            float e0 = expf(a0 - mx), e1 = expf(a1 - mx), e2 = expf(a2 - mx), e3 = expf(a3 - mx);
            float su = warp_sum(e0 + e1 + e2 + e3);
            float inv = 1.f / su;
            s.cw[lane] = e0 * inv; s.cw[lane + 32] = e1 * inv;
            s.cw[lane + 64] = e2 * inv; s.cw[lane + 96] = e3 * inv;
        } else if (tid >= 128 && tid < 256) {
            int e = tid - 128;
            float ue = s.usage[e];
            int cnt = 0;
            #pragma unroll 8
            for (int j = 0; j < 128; j++) {
                float uj = s.usage[j];
                cnt += (uj < ue) || (uj == ue && j < e);
            }
            s.skv[cnt] = ue; s.ski[cnt] = e;
        }
        __syncthreads();

        // ==== X3+X4 ====
        if (wi == 0) {
            float running = 1.f;
            #pragma unroll
            for (int r = 0; r < 4; r++) {
                float v0 = s.skv[r * 32 + lane];
                int   ix = s.ski[r * 32 + lane];
                float c = v0;
                #pragma unroll
                for (int off = 1; off < 32; off <<= 1) {
                    float tsh = __shfl_up_sync(0xffffffffu, c, off);
                    if (lane >= off) c *= tsh;
                }
                float excl_in = __shfl_up_sync(0xffffffffu, c, 1);
                float excl = (lane == 0) ? running : excl_in * running;
                s.aalloc[ix] = (1.f - v0) * excl;
                running *= __shfl_sync(0xffffffffu, c, 31);
            }
            __syncwarp();
            float ag = s.sc[1], wg = s.sc[2];
            #pragma unroll
            for (int o = 0; o < 4; o++) {
                int n = lane + o * 32;
                s.ww[n] = wg * (ag * s.aalloc[n] + (1.f - ag) * s.cw[n]);
            }
        }
        __syncthreads();

        // ==== X5+X6 ====
        {
            const int ti = (tid >> 5) * 4;
            const int tj = (tid & 31) * 4;
            float wwi[4], nv[4][4];
            #pragma unroll
            for (int r = 0; r < 4; r++) wwi[r] = s.ww[ti + r];
            float4 wwj4 = *reinterpret_cast<const float4*>(&s.ww[tj]);
            float4 pj4  = *reinterpret_cast<const float4*>(&s.prec[tj]);
            #pragma unroll
            for (int r = 0; r < 4; r++) {
                float4 lo = *reinterpret_cast<const float4*>(&s.link[(ti + r) * LINKS_ + tj]);
                nv[r][0] = (1.f - wwi[r] - wwj4.x) * lo.x + wwi[r] * pj4.x;
                nv[r][1] = (1.f - wwi[r] - wwj4.y) * lo.y + wwi[r] * pj4.y;
                nv[r][2] = (1.f - wwi[r] - wwj4.z) * lo.z + wwi[r] * pj4.z;
                nv[r][3] = (1.f - wwi[r] - wwj4.w) * lo.w + wwi[r] * pj4.w;
                #pragma unroll
                for (int cc = 0; cc < 4; cc++)
                    if (ti + r == tj + cc) nv[r][cc] = 0.f;
                *reinterpret_cast<float4*>(&s.link[(ti + r) * LINKS_ + tj]) =
                    make_float4(nv[r][0], nv[r][1], nv[r][2], nv[r][3]);
            }
            #pragma unroll
            for (int cc = 0; cc < 4; cc++)
                *reinterpret_cast<float4*>(&s.linkT[(tj + cc) * LINKS_ + ti]) =
                    make_float4(nv[0][cc], nv[1][cc], nv[2][cc], nv[3][cc]);
        }
        if (tid < 512) {
            const int row = tid >> 2, sub = tid & 3;
            const int w0 = sub * 16;
            float wwn = s.ww[row];
            float sq = 0.f;
            #pragma unroll
            for (int q = 0; q < 4; q++) {
                float4 m  = *reinterpret_cast<const float4*>(&s.M[row * MS_ + w0 + q * 4]);
                float4 ev = *reinterpret_cast<const float4*>(&s.erasev[w0 + q * 4]);
                float4 wv = *reinterpret_cast<const float4*>(&s.wvec[w0 + q * 4]);
                m.x = m.x * (1.f - wwn * ev.x) + wwn * wv.x;
                m.y = m.y * (1.f - wwn * ev.y) + wwn * wv.y;
                m.z = m.z * (1.f - wwn * ev.z) + wwn * wv.z;
                m.w = m.w * (1.f - wwn * ev.w) + wwn * wv.w;
                sq += m.x * m.x + m.y * m.y + m.z * m.z + m.w * m.w;
                *reinterpret_cast<float4*>(&s.M[row * MS_ + w0 + q * 4]) = m;
            }
            sq += __shfl_xor_sync(0xffffffffu, sq, 1);
            sq += __shfl_xor_sync(0xffffffffu, sq, 2);
            if (sub == 0) s.Mnorm[row] = sqrtf(sq);
        } else if (wi == 16) {
            float ssum = warp_sum(s.ww[lane] + s.ww[lane + 32] + s.ww[lane + 64] + s.ww[lane + 96]);
            if (lane == 0) s.sc[4] = ssum;
        }
        __syncthreads();

        // ==== X7+X8: one thread per row computes ALL 4 r-dots (link read once) ====
        if (tid < 128) {
            const int i = tid;
            const float4* lr  = reinterpret_cast<const float4*>(&s.link[i * LINKS_]);
            const float4* w0p = reinterpret_cast<const float4*>(&s.wr[0]);
            const float4* w1p = reinterpret_cast<const float4*>(&s.wr[128]);
            const float4* w2p = reinterpret_cast<const float4*>(&s.wr[256]);
            const float4* w3p = reinterpret_cast<const float4*>(&s.wr[384]);
            float a0 = 0.f, a1 = 0.f, a2 = 0.f, a3 = 0.f;
            #pragma unroll 8
            for (int q = 0; q < 32; q++) {
                float4 l4 = lr[q];
                a0 += dot4(l4, w0p[q]); a1 += dot4(l4, w1p[q]);
                a2 += dot4(l4, w2p[q]); a3 += dot4(l4, w3p[q]);
            }
            s.fw[i] = a0; s.fw[128 + i] = a1; s.fw[256 + i] = a2; s.fw[384 + i] = a3;
        } else if (tid < 256) {
            const int i = tid - 128;
            const float4* lr  = reinterpret_cast<const float4*>(&s.linkT[i * LINKS_]);
            const float4* w0p = reinterpret_cast<const float4*>(&s.wr[0]);
            const float4* w1p = reinterpret_cast<const float4*>(&s.wr[128]);
            const float4* w2p = reinterpret_cast<const float4*>(&s.wr[256]);
            const float4* w3p = reinterpret_cast<const float4*>(&s.wr[384]);
            float a0 = 0.f, a1 = 0.f, a2 = 0.f, a3 = 0.f;
            #pragma unroll 8
            for (int q = 0; q < 32; q++) {
                float4 l4 = lr[q];
                a0 += dot4(l4, w0p[q]); a1 += dot4(l4, w1p[q]);
                a2 += dot4(l4, w2p[q]); a3 += dot4(l4, w3p[q]);
            }
            s.bw[i] = a0; s.bw[128 + i] = a1; s.bw[256 + i] = a2; s.bw[384 + i] = a3;
        } else if (tid < 384) {
            const int n = tid - 256;
            const float4* mr  = reinterpret_cast<const float4*>(&s.M[n * MS_]);
            const float4* k0p = reinterpret_cast<const float4*>(&s.v[0]);
            const float4* k1p = reinterpret_cast<const float4*>(&s.v[64]);
            const float4* k2p = reinterpret_cast<const float4*>(&s.v[128]);
            const float4* k3p = reinterpret_cast<const float4*>(&s.v[192]);
            float d0 = 0.f, d1 = 0.f, d2 = 0.f, d3 = 0.f;
            #pragma unroll 8
            for (int q = 0; q < 16; q++) {
                float4 m4 = mr[q];
                d0 += dot4(m4, k0p[q]); d1 += dot4(m4, k1p[q]);
                d2 += dot4(m4, k2p[q]); d3 += dot4(m4, k3p[q]);
            }
            float base = 1.f / (s.Mnorm[n] + EPS_);
            s.crs[n]       = s.rb[0] * d0 * base / (s.keynorm[0] + EPS_);
            s.crs[128 + n] = s.rb[1] * d1 * base / (s.keynorm[1] + EPS_);
            s.crs[256 + n] = s.rb[2] * d2 * base / (s.keynorm[2] + EPS_);
            s.crs[384 + n] = s.rb[3] * d3 * base / (s.keynorm[3] + EPS_);
        } else if (wi == 12) {
            float ssum = s.sc[4];
            #pragma unroll
            for (int o = 0; o < 4; o++) {
                int n = lane + o * 32;
                s.prec[n] = (1.f - ssum) * s.prec[n] + s.ww[n];
            }
        }
        __syncthreads();

        // ==== X9+X10: per-r read softmax + wr write (warps 0-3) ====
        if (wi < 4) {
            int r = wi;
            float a0 = s.crs[r * N_ + lane],      a1 = s.crs[r * N_ + lane + 32];
            float a2 = s.crs[r * N_ + lane + 64], a3 = s.crs[r * N_ + lane + 96];
            float mx = warp_max(fmaxf(fmaxf(a0, a1), fmaxf(a2, a3)));
            float e0 = expf(a0 - mx), e1 = expf(a1 - mx), e2 = expf(a2 - mx), e3 = expf(a3 - mx);
            float su = warp_sum(e0 + e1 + e2 + e3);
            float inv = 1.f / su;
            float m0 = s.modes[3 * r], m1 = s.modes[3 * r + 1], m2 = s.modes[3 * r + 2];
            #pragma unroll
            for (int o = 0; o < 4; o++) {
                int n = lane + o * 32;
                float cv = (o == 0 ? e0 : o == 1 ? e1 : o == 2 ? e2 : e3) * inv;
                s.wr[r * 128 + n] = m0 * s.bw[r * 128 + n] + m1 * cv + m2 * s.fw[r * 128 + n];
            }
        }
        __syncthreads();

        // ==== X11: reads_n = wr_n @ M ====
        {
            int outi = tid & 255;
            int chunk = tid >> 8;
            int r = outi >> 6, w = outi & 63;
            float acc = 0.f;
            int n0 = chunk * 32;
            #pragma unroll 4
            for (int n = n0; n < n0 + 32; n++)
                acc = fmaf(s.wr[r * 128 + n], s.M[n * MS_ + w], acc);
            s.zbuf[chunk * 256 + outi] = acc;
        }
        __syncthreads();
        if (tid < 256)
            s.act[512 + tid] = s.zbuf[tid] + s.zbuf[256 + tid] + s.zbuf[512 + tid] + s.zbuf[768 + tid];
        __syncthreads();
    }

    // ==== final out GEMM for t = T-1 ====
    {
        const int grp  = tid & 15;
        const int part = tid >> 4;
        const int cg8  = grp * 8;
        const int colg = k * 128 + cg8;
        float a0 = 0.f, a1 = 0.f, a2 = 0.f, a3 = 0.f;
        float a4 = 0.f, a5 = 0.f, a6 = 0.f, a7 = 0.f;
        const int r0 = part * 12;
        #pragma unroll
        for (int i = r0; i < r0 + 12; i++) {
            float sv = s.act[512 + i];
            uint4 wp = *reinterpret_cast<const uint4*>(&g_wo[(size_t)i * OUT_ + colg]);
            const __half2* h2 = reinterpret_cast<const __half2*>(&wp);
            float2 f0 = __half22float2(h2[0]);
            float2 f1 = __half22float2(h2[1]);
            float2 f2 = __half22float2(h2[2]);
            float2 f3 = __half22float2(h2[3]);
            a0 = fmaf(sv, f0.x, a0); a1 = fmaf(sv, f0.y, a1);
            a2 = fmaf(sv, f1.x, a2); a3 = fmaf(sv, f1.y, a3);
            a4 = fmaf(sv, f2.x, a4); a5 = fmaf(sv, f2.y, a5);
            a6 = fmaf(sv, f3.x, a6); a7 = fmaf(sv, f3.y, a7);
        }
        *reinterpret_cast<float4*>(&s.zbuf[part * 128 + cg8])     = make_float4(a0, a1, a2, a3);
        *reinterpret_cast<float4*>(&s.zbuf[part * 128 + cg8 + 4]) = make_float4(a4, a5, a6, a7);
    }
    __syncthreads();
    if (tid < 128) {
        float acc = bo[k * 128 + tid];
        #pragma unroll
        for (int p = 0; p < 64; p++) acc += s.zbuf[p * 128 + tid];
        out[(size_t)b * T_ * OUT_ + (size_t)(T_ - 1) * OUT_ + k * 128 + tid] = acc;
    }
}

extern "C" void kernel_launch(void* const* d_in, const int* in_sizes, int n_in,
                              void* d_out, int out_size) {
    (void)in_sizes; (void)n_in; (void)out_size;
    const float* x   = (const float*)d_in[0];
    const float* Wx  = (const float*)d_in[1];
    const float* Wh  = (const float*)d_in[2];
    const float* bl  = (const float*)d_in[3];
    const float* Wif = (const float*)d_in[4];
    const float* bif = (const float*)d_in[5];
    const float* Wo  = (const float*)d_in[6];
    const float* bo  = (const float*)d_in[7];
    float* out = (float*)d_out;

    cvt_lstm<<<(768 * GATES_ / 2 + 1023) / 1024, 1024>>>(Wx, Wh);
    cvt_wo<<<(768 * OUT_ / 2 + 1023) / 1024, 1024>>>(Wo);
    cvt_wif<<<(512 * 480 + 1023) / 1024, 1024>>>(Wif);

    dim3 pg(B_ * T_ / 128, GATES_ / 128);
    xz_kernel<<<pg, 256>>>(x, Wx);

    cudaFuncSetAttribute(dnc_kernel, cudaFuncAttributeMaxDynamicSharedMemorySize,
                         (int)sizeof(Smem));
    dnc_kernel<<<B_ * CL_, 1024, sizeof(Smem)>>>(bl, bif, bo, out);
}